// round 11
// baseline (speedup 1.0000x reference)
#include <cuda_runtime.h>
#include <cuda_bf16.h>
#include <cuda_fp16.h>
#include <cstdint>

#define Bz    2
#define Sq    2048
#define DIM   1024
#define Hn    16
#define DHd   64
#define INNER 1024
#define TOK   4096

// ---------------------------------------------------------------------------
// Scratch (device globals). Fragment arrays are uint32 (packed 16-bit x2).
// ---------------------------------------------------------------------------
__device__ uint32_t g_xn_h[TOK*DIM/2],     g_xn_l[TOK*DIM/2];   // bf16 hi/lo A-frags
__device__ uint32_t g_xn16[TOK*DIM/2];                          // fp16 single A-frags
__device__ uint32_t g_wqk_h[DIM*2048/2],   g_wqk_l[DIM*2048/2]; // Wq|Wk bf16 B-frags
__device__ uint32_t g_wv16[DIM*INNER/2];                        // Wv fp16 B-frags
__device__ uint32_t g_wo16[INNER*DIM/2];                        // Wo fp16 B-frags
__device__ float    g_qk[TOK*2048];                             // q|k projection (fp32)
__device__ float    g_v [TOK*INNER];                            // v projection (fp32)
__device__ uint32_t g_qf_h[TOK*INNER/2],   g_qf_l[TOK*INNER/2]; // fp16 hi/lo
__device__ uint32_t g_kf_h[TOK*INNER/2],   g_kf_l[TOK*INNER/2]; // fp16 hi/lo
__device__ uint32_t g_vf  [TOK*INNER/2];                        // fp16 single
__device__ uint32_t g_ao16[TOK*INNER/2];                        // attn out fp16 A-frags

// ---------------------------------------------------------------------------
// Helpers
// ---------------------------------------------------------------------------
__device__ __forceinline__ uint32_t smem_u32(const void* p) {
    uint32_t a;
    asm("{ .reg .u64 t; cvta.to.shared.u64 t, %1; cvt.u32.u64 %0, t; }" : "=r"(a) : "l"(p));
    return a;
}
__device__ __forceinline__ uint32_t pkbf(float a, float b) {
    return (uint32_t)__bfloat16_as_ushort(__float2bfloat16_rn(a)) |
           ((uint32_t)__bfloat16_as_ushort(__float2bfloat16_rn(b)) << 16);
}
__device__ __forceinline__ void splitbf(float a, float b, uint32_t& hi, uint32_t& lo) {
    __nv_bfloat16 ha = __float2bfloat16_rn(a), hb = __float2bfloat16_rn(b);
    hi = (uint32_t)__bfloat16_as_ushort(ha) | ((uint32_t)__bfloat16_as_ushort(hb) << 16);
    lo = pkbf(a - __bfloat162float(ha), b - __bfloat162float(hb));
}
__device__ __forceinline__ uint32_t pkh2(float a, float b) {
    __half2 h = __floats2half2_rn(a, b);
    return *(uint32_t*)&h;
}
__device__ __forceinline__ void splitf16(float a, float b, uint32_t& hi, uint32_t& lo) {
    __half ha = __float2half_rn(a), hb = __float2half_rn(b);
    __half2 hp = __halves2half2(ha, hb);
    hi = *(uint32_t*)&hp;
    lo = pkh2(a - __half2float(ha), b - __half2float(hb));
}
__device__ __forceinline__ float ex2(float x) {
    float y;
    asm("ex2.approx.f32 %0, %1;" : "=f"(y) : "f"(x));
    return y;
}
// exp2 of two fp32 values -> packed fp16x2 {lo=exp2(a), hi=exp2(b)}
__device__ __forceinline__ uint32_t ex2h2(float a, float b) {
    uint32_t r;
    asm("{ .reg .b32 t; cvt.rn.f16x2.f32 t, %2, %1; ex2.approx.f16x2 %0, t; }"
        : "=r"(r) : "f"(a), "f"(b));
    return r;
}
__device__ __forceinline__ uint32_t hadd2u(uint32_t a, uint32_t b) {
    uint32_t r;
    asm("add.f16x2 %0, %1, %2;" : "=r"(r) : "r"(a), "r"(b));
    return r;
}
__device__ __forceinline__ float2 h22f2(uint32_t h) {
    __half2 hh = *(__half2*)&h;
    return __half22float2(hh);
}
__device__ __forceinline__ void mma_bf(float* c, const uint32_t* a, const uint32_t* b) {
    asm volatile(
        "mma.sync.aligned.m16n8k16.row.col.f32.bf16.bf16.f32 "
        "{%0,%1,%2,%3}, {%4,%5,%6,%7}, {%8,%9}, {%0,%1,%2,%3};"
        : "+f"(c[0]), "+f"(c[1]), "+f"(c[2]), "+f"(c[3])
        : "r"(a[0]), "r"(a[1]), "r"(a[2]), "r"(a[3]), "r"(b[0]), "r"(b[1]));
}
__device__ __forceinline__ void mma_f16(float* c, const uint32_t* a, const uint32_t* b) {
    asm volatile(
        "mma.sync.aligned.m16n8k16.row.col.f32.f16.f16.f32 "
        "{%0,%1,%2,%3}, {%4,%5,%6,%7}, {%8,%9}, {%0,%1,%2,%3};"
        : "+f"(c[0]), "+f"(c[1]), "+f"(c[2]), "+f"(c[3])
        : "r"(a[0]), "r"(a[1]), "r"(a[2]), "r"(a[3]), "r"(b[0]), "r"(b[1]));
}
__device__ __forceinline__ void cpa16(uint32_t saddr, const void* gptr) {
    asm volatile("cp.async.cg.shared.global [%0], [%1], 16;" :: "r"(saddr), "l"(gptr) : "memory");
}
__device__ __forceinline__ void cp_commit() { asm volatile("cp.async.commit_group;" ::: "memory"); }
template <int N> __device__ __forceinline__ void cp_wait() {
    asm volatile("cp.async.wait_group %0;" :: "n"(N) : "memory");
}

// B-fragment index: (pair p of K, col n), KS16 = K/16
__device__ __forceinline__ size_t bfrag_idx(int p, int n, int KS16, int ntOff) {
    return ((size_t)((ntOff + (n >> 3)) * KS16 + (p >> 3))) * 64 +
           ((n & 7) * 4 + (p & 3)) * 2 + ((p >> 2) & 1);
}

// ---------------------------------------------------------------------------
// 1) Prep: blocks [0,4096) LayerNorm; [4096,6144) Wq; [6144,10240) Wkv split;
//    [10240,12288) Wo.
// ---------------------------------------------------------------------------
__global__ void __launch_bounds__(256) prep_kernel(const float* __restrict__ x,
                                                   const float* __restrict__ w,
                                                   const float* __restrict__ bias,
                                                   uint32_t* __restrict__ xh,
                                                   uint32_t* __restrict__ xl,
                                                   uint32_t* __restrict__ x16,
                                                   const float* __restrict__ Wq,
                                                   const float* __restrict__ Wkv,
                                                   const float* __restrict__ Wo,
                                                   uint32_t* __restrict__ wqkh,
                                                   uint32_t* __restrict__ wqkl,
                                                   uint32_t* __restrict__ wv16,
                                                   uint32_t* __restrict__ wo16) {
    const int bid = blockIdx.x;
    if (bid >= TOK) {
        const int r = bid - TOK;
        if (r < 2048) {
            const int id = r * 256 + threadIdx.x;
            const int p = id >> 10, n = id & 1023;
            const float a = Wq[(size_t)(2 * p) * 1024 + n];
            const float b = Wq[(size_t)(2 * p + 1) * 1024 + n];
            uint32_t hi, lo;
            splitbf(a, b, hi, lo);
            const size_t idx = bfrag_idx(p, n, 64, 0);
            wqkh[idx] = hi; wqkl[idx] = lo;
        } else if (r < 6144) {
            const int id = (r - 2048) * 256 + threadIdx.x;
            const int p = id >> 11, n = id & 2047;
            const float a = Wkv[(size_t)(2 * p) * 2048 + n];
            const float b = Wkv[(size_t)(2 * p + 1) * 2048 + n];
            if (n < 1024) {
                uint32_t hi, lo;
                splitbf(a, b, hi, lo);
                const size_t idx = bfrag_idx(p, n, 64, 128);
                wqkh[idx] = hi; wqkl[idx] = lo;
            } else {
                wv16[bfrag_idx(p, n - 1024, 64, 0)] = pkh2(a, b);
            }
        } else {
            const int id = (r - 6144) * 256 + threadIdx.x;
            const int p = id >> 10, n = id & 1023;
            const float a = Wo[(size_t)(2 * p) * 1024 + n];
            const float b = Wo[(size_t)(2 * p + 1) * 1024 + n];
            wo16[bfrag_idx(p, n, 64, 0)] = pkh2(a, b);
        }
        return;
    }
    const int row = bid;
    const float* xr = x + (size_t)row * DIM;
    float2 v[2];
    v[0] = *(const float2*)(xr + 2 * threadIdx.x);
    v[1] = *(const float2*)(xr + 2 * (threadIdx.x + 256));
    float s  = v[0].x + v[0].y + v[1].x + v[1].y;
    float sq = v[0].x * v[0].x + v[0].y * v[0].y + v[1].x * v[1].x + v[1].y * v[1].y;
#pragma unroll
    for (int off = 16; off; off >>= 1) {
        s  += __shfl_xor_sync(0xffffffffu, s, off);
        sq += __shfl_xor_sync(0xffffffffu, sq, off);
    }
    __shared__ float red[2][8];
    const int warp = threadIdx.x >> 5, lane = threadIdx.x & 31;
    if (lane == 0) { red[0][warp] = s; red[1][warp] = sq; }
    __syncthreads();
    float ts = 0.f, tq2 = 0.f;
#pragma unroll
    for (int i = 0; i < 8; i++) { ts += red[0][i]; tq2 += red[1][i]; }
    const float mean = ts * (1.0f / DIM);
    const float var  = tq2 * (1.0f / DIM) - mean * mean;
    const float rstd = rsqrtf(var + 1e-5f);
    const int mt = row >> 4, mr = row & 15, g = mr & 7, hih = mr >> 3;
#pragma unroll
    for (int i = 0; i < 2; i++) {
        const int p = threadIdx.x + i * 256;
        const float2 wv = *(const float2*)(w + 2 * p);
        const float2 bv = *(const float2*)(bias + 2 * p);
        const float y0 = wv.x * (v[i].x - mean) * rstd + bv.x;
        const float y1 = wv.y * (v[i].y - mean) * rstd + bv.y;
        const int ks = p >> 3, c = p & 7, tq = c & 3, ch = c >> 2;
        const size_t idx = ((size_t)(mt * 64 + ks)) * 128 + (g * 4 + tq) * 4 + hih + 2 * ch;
        uint32_t hi, lo;
        splitbf(y0, y1, hi, lo);
        xh[idx] = hi; xl[idx] = lo;
        x16[idx] = pkh2(y0, y1);
    }
}

// ---------------------------------------------------------------------------
// 2a) bf16x3 GEMM body: 128x128 tile, BK=32, 2-stage cp.async.
// ---------------------------------------------------------------------------
__device__ __forceinline__ void gemm_bf3_body(const uint32_t* __restrict__ Ah,
                                              const uint32_t* __restrict__ Al,
                                              const uint32_t* __restrict__ Bh,
                                              const uint32_t* __restrict__ Bl,
                                              float* __restrict__ C,
                                              int N, int K, int bm, int bn,
                                              uint32_t* sm) {
    const int tid = threadIdx.x, wid = tid >> 5, lane = tid & 31;
    const int wr = wid >> 2, wc = wid & 3, g = lane >> 2, tq = lane & 3;
    const int KS = K >> 4, NSTG = K >> 5;
    const uint32_t sbase = smem_u32(sm);

    const uint32_t* Ah0 = Ah + (size_t)(bm >> 4) * KS * 128;
    const uint32_t* Al0 = Al + (size_t)(bm >> 4) * KS * 128;
    const uint32_t* Bh0 = Bh + (size_t)(bn >> 3) * KS * 64;
    const uint32_t* Bl0 = Bl + (size_t)(bn >> 3) * KS * 64;

    float acc[4][4][4];
#pragma unroll
    for (int i = 0; i < 4; i++)
#pragma unroll
        for (int j = 0; j < 4; j++)
#pragma unroll
            for (int e = 0; e < 4; e++) acc[i][j][e] = 0.f;

#define G_ISSUE(S, BUF) do {                                                        \
    const uint32_t sb_ = sbase + (uint32_t)(BUF) * 32768u;                          \
    _Pragma("unroll")                                                               \
    for (int i_ = 0; i_ < 2; i_++) {                                                \
        const int f_ = tid + i_ * 256;                                              \
        const int mt_ = f_ >> 6, wA_ = (4 * f_) & 255;                              \
        const int ksA_ = wA_ >> 7, frA_ = wA_ & 127;                                \
        const size_t oa_ = ((size_t)mt_ * KS + (S) * 2 + ksA_) * 128 + frA_;        \
        cpa16(sb_ + f_ * 16u,           Ah0 + oa_);                                 \
        cpa16(sb_ + 8192u + f_ * 16u,   Al0 + oa_);                                 \
        const int nt_ = f_ >> 5, wB_ = (4 * f_) & 127;                              \
        const int ksB_ = wB_ >> 6, frB_ = wB_ & 63;                                 \
        const size_t ob_ = ((size_t)nt_ * KS + (S) * 2 + ksB_) * 64 + frB_;         \
        cpa16(sb_ + 16384u + f_ * 16u,  Bh0 + ob_);                                 \
        cpa16(sb_ + 24576u + f_ * 16u,  Bl0 + ob_);                                 \
    }                                                                               \
    cp_commit();                                                                    \
} while (0)

    G_ISSUE(0, 0);
    int buf = 0;
    for (int s = 0; s < NSTG; s++) {
        if (s + 1 < NSTG) { G_ISSUE(s + 1, buf ^ 1); cp_wait<1>(); }
        else              { cp_wait<0>(); }
        __syncthreads();
        const uint32_t* S0 = sm + buf * 8192;
#pragma unroll
        for (int ksl = 0; ksl < 2; ksl++) {
            uint4 ah[4], al[4];
            uint2 bh[4], bl[4];
#pragma unroll
            for (int i = 0; i < 4; i++) {
                const int mt = wr * 4 + i;
                ah[i] = *(const uint4*)(S0 + (mt * 2 + ksl) * 128 + (g * 4 + tq) * 4);
                al[i] = *(const uint4*)(S0 + 2048 + (mt * 2 + ksl) * 128 + (g * 4 + tq) * 4);
            }
#pragma unroll
            for (int j = 0; j < 4; j++) {
                const int nt = wc * 4 + j;
                bh[j] = *(const uint2*)(S0 + 4096 + (nt * 2 + ksl) * 64 + (g * 4 + tq) * 2);
                bl[j] = *(const uint2*)(S0 + 6144 + (nt * 2 + ksl) * 64 + (g * 4 + tq) * 2);
            }
#pragma unroll
            for (int i = 0; i < 4; i++)
#pragma unroll
                for (int j = 0; j < 4; j++) {
                    mma_bf(acc[i][j], (const uint32_t*)&ah[i], (const uint32_t*)&bh[j]);
                    mma_bf(acc[i][j], (const uint32_t*)&ah[i], (const uint32_t*)&bl[j]);
                    mma_bf(acc[i][j], (const uint32_t*)&al[i], (const uint32_t*)&bh[j]);
                }
        }
        __syncthreads();
        buf ^= 1;
    }
#undef G_ISSUE

#pragma unroll
    for (int i = 0; i < 4; i++) {
        const int r0 = bm + (wr * 4 + i) * 16 + g;
#pragma unroll
        for (int j = 0; j < 4; j++) {
            const int c0 = bn + (wc * 4 + j) * 8 + 2 * tq;
            *(float2*)(C + (size_t)r0 * N + c0)       = make_float2(acc[i][j][0], acc[i][j][1]);
            *(float2*)(C + (size_t)(r0 + 8) * N + c0) = make_float2(acc[i][j][2], acc[i][j][3]);
        }
    }
}

// ---------------------------------------------------------------------------
// 2b) fp16-single GEMM body: 128x128 tile, BK=64, 2-stage cp.async, 1 MMA.
// ---------------------------------------------------------------------------
__device__ __forceinline__ void gemm_f16s_body(const uint32_t* __restrict__ Af,
                                               const uint32_t* __restrict__ Bf,
                                               float* __restrict__ C,
                                               int N, int K, int bm, int bn,
                                               uint32_t* sm) {
    const int tid = threadIdx.x, wid = tid >> 5, lane = tid & 31;
    const int wr = wid >> 2, wc = wid & 3, g = lane >> 2, tq = lane & 3;
    const int KS = K >> 4, NSTG = K >> 6;
    const uint32_t sbase = smem_u32(sm);

    const uint32_t* A0g = Af + (size_t)(bm >> 4) * KS * 128;
    const uint32_t* B0g = Bf + (size_t)(bn >> 3) * KS * 64;

    float acc[4][4][4];
#pragma unroll
    for (int i = 0; i < 4; i++)
#pragma unroll
        for (int j = 0; j < 4; j++)
#pragma unroll
            for (int e = 0; e < 4; e++) acc[i][j][e] = 0.f;

#define F_ISSUE(S, BUF) do {                                                        \
    const uint32_t sb_ = sbase + (uint32_t)(BUF) * 32768u;                          \
    _Pragma("unroll")                                                               \
    for (int i_ = 0; i_ < 4; i_++) {                                                \
        const int f_ = tid + i_ * 256;                                              \
        const int mt_ = f_ >> 7, wA_ = (4 * f_) & 511;                              \
        const int ksA_ = wA_ >> 7, frA_ = wA_ & 127;                                \
        const size_t oa_ = ((size_t)mt_ * KS + (S) * 4 + ksA_) * 128 + frA_;        \
        cpa16(sb_ + f_ * 16u, A0g + oa_);                                           \
        const int nt_ = f_ >> 6, wB_ = (4 * f_) & 255;                              \
        const int ksB_ = wB_ >> 6, frB_ = wB_ & 63;                                 \
        const size_t ob_ = ((size_t)nt_ * KS + (S) * 4 + ksB_) * 64 + frB_;         \
        cpa16(sb_ + 16384u + f_ * 16u, B0g + ob_);                                  \
    }                                                                               \
    cp_commit();                                                                    \
} while (0)

    F_ISSUE(0, 0);
    int buf = 0;
    for (int s = 0; s < NSTG; s++) {
        if (s + 1 < NSTG) { F_ISSUE(s + 1, buf ^ 1); cp_wait<1>(); }
        else              { cp_wait<0>(); }
        __syncthreads();
        const uint32_t* S0 = sm + buf * 8192;
#pragma unroll
        for (int ksl = 0; ksl < 4; ksl++) {
            uint4 a[4];
            uint2 b[4];
#pragma unroll
            for (int i = 0; i < 4; i++)
                a[i] = *(const uint4*)(S0 + ((wr * 4 + i) * 4 + ksl) * 128 + (g * 4 + tq) * 4);
#pragma unroll
            for (int j = 0; j < 4; j++)
                b[j] = *(const uint2*)(S0 + 4096 + ((wc * 4 + j) * 4 + ksl) * 64 + (g * 4 + tq) * 2);
#pragma unroll
            for (int i = 0; i < 4; i++)
#pragma unroll
                for (int j = 0; j < 4; j++)
                    mma_f16(acc[i][j], (const uint32_t*)&a[i], (const uint32_t*)&b[j]);
        }
        __syncthreads();
        buf ^= 1;
    }
#undef F_ISSUE

#pragma unroll
    for (int i = 0; i < 4; i++) {
        const int r0 = bm + (wr * 4 + i) * 16 + g;
#pragma unroll
        for (int j = 0; j < 4; j++) {
            const int c0 = bn + (wc * 4 + j) * 8 + 2 * tq;
            *(float2*)(C + (size_t)r0 * N + c0)       = make_float2(acc[i][j][0], acc[i][j][1]);
            *(float2*)(C + (size_t)(r0 + 8) * N + c0) = make_float2(acc[i][j][2], acc[i][j][3]);
        }
    }
}

// Fused QK (bf16x3) + V (fp16) projection: grid (24, 32).
__global__ void __launch_bounds__(256, 2) proj_fused(const uint32_t* __restrict__ xh,
                                                     const uint32_t* __restrict__ xl,
                                                     const uint32_t* __restrict__ x16,
                                                     const uint32_t* __restrict__ wqkh,
                                                     const uint32_t* __restrict__ wqkl,
                                                     const uint32_t* __restrict__ wv16,
                                                     float* __restrict__ qk,
                                                     float* __restrict__ v) {
    extern __shared__ uint32_t sm[];
    if (blockIdx.x < 16)
        gemm_bf3_body(xh, xl, wqkh, wqkl, qk, 2048, 1024,
                      blockIdx.y * 128, blockIdx.x * 128, sm);
    else
        gemm_f16s_body(x16, wv16, v, 1024, 1024,
                       blockIdx.y * 128, (blockIdx.x - 16) * 128, sm);
}

// Standalone fp16-single GEMM (output projection).
__global__ void __launch_bounds__(256, 2) gemm_f16s(const uint32_t* __restrict__ Af,
                                                    const uint32_t* __restrict__ Bf,
                                                    float* __restrict__ C,
                                                    int N, int K) {
    extern __shared__ uint32_t sm[];
    gemm_f16s_body(Af, Bf, C, N, K, blockIdx.y * 128, blockIdx.x * 128, sm);
}

// ---------------------------------------------------------------------------
// 3) RMSNorm + head-split: Q, K -> fp16 hi/lo frags; V -> single fp16 B-frags.
// ---------------------------------------------------------------------------
#define LOG2E 1.4426950408889634f

__global__ void __launch_bounds__(256) rms_kernel(const float* __restrict__ qk,
                                                  const float* __restrict__ vv,
                                                  const float* __restrict__ qg,
                                                  const float* __restrict__ kg,
                                                  uint32_t* __restrict__ qfh, uint32_t* __restrict__ qfl,
                                                  uint32_t* __restrict__ kfh, uint32_t* __restrict__ kfl,
                                                  uint32_t* __restrict__ vf) {
    const int tk0 = blockIdx.x * 2;
    const int warp = threadIdx.x >> 5, lane = threadIdx.x & 31;
    const int b = tk0 >> 11, s0 = tk0 & 2047;
    const int ks = lane >> 3, c = lane & 7, tq = c & 3, ch = c >> 2;
#pragma unroll
    for (int i = 0; i < 2; i++) {
        const int h = warp * 2 + i;
        const int bh = b * 16 + h;
        const float2 gq = *(const float2*)(qg + h * 64 + 2 * lane);
        const float2 gk = *(const float2*)(kg + h * 64 + 2 * lane);
#pragma unroll
        for (int tt = 0; tt < 2; tt++) {
            const int token = tk0 + tt, s = s0 + tt;
            {
                const float2 qv = *(const float2*)(qk + (size_t)token * 2048 + h * 64 + 2 * lane);
                float ss = qv.x * qv.x + qv.y * qv.y;
#pragma unroll
                for (int off = 16; off; off >>= 1) ss += __shfl_xor_sync(0xffffffffu, ss, off);
                const float r = rsqrtf(ss * (1.0f / DHd) + 1e-8f) * (8.0f * LOG2E);
                const int mt = s >> 4, mr = s & 15, gg = mr & 7, hih = mr >> 3;
                const size_t qi = ((size_t)(bh * 128 + mt) * 4 + ks) * 128 + (gg * 4 + tq) * 4 + hih + 2 * ch;
                uint32_t hi, lo;
                splitf16(qv.x * r * gq.x, qv.y * r * gq.y, hi, lo);
                qfh[qi] = hi; qfl[qi] = lo;
            }
            {
                const float2 kvv = *(const float2*)(qk + (size_t)token * 2048 + 1024 + h * 64 + 2 * lane);
                float ss = kvv.x * kvv.x + kvv.y * kvv.y;
#pragma unroll
                for (int off = 16; off; off >>= 1) ss += __shfl_xor_sync(0xffffffffu, ss, off);
                const float r = rsqrtf(ss * (1.0f / DHd) + 1e-8f) * 8.0f;
                const int nt = s >> 3, gg = s & 7;
                const size_t ki = ((size_t)(bh * 256 + nt) * 4 + ks) * 64 + (gg * 4 + tq) * 2 + ch;
                uint32_t hi, lo;
                splitf16(kvv.x * r * gk.x, kvv.y * r * gk.y, hi, lo);
                kfh[ki] = hi; kfl[ki] = lo;
            }
        }
        {
            const float2 va = *(const float2*)(vv + (size_t)tk0 * 1024 + h * 64 + 2 * lane);
            const float2 vb = *(const float2*)(vv + (size_t)(tk0 + 1) * 1024 + h * 64 + 2 * lane);
            const int pq = s0 >> 1;
            const int ksv = pq >> 3, cv = pq & 7, tv = cv & 3, rv = cv >> 2;
            const int d0 = 2 * lane;
            const size_t vi0 = ((size_t)(bh * 128 + ksv) * 8 + (d0 >> 3)) * 64 + ((d0 & 7) * 4 + tv) * 2 + rv;
            const size_t vi1 = ((size_t)(bh * 128 + ksv) * 8 + ((d0 + 1) >> 3)) * 64 + (((d0 + 1) & 7) * 4 + tv) * 2 + rv;
            vf[vi0] = pkh2(va.x, vb.x);
            vf[vi1] = pkh2(va.y, vb.y);
        }
    }
}

// ---------------------------------------------------------------------------
// 4) Flash attention, fp16 MMA, software-pipelined: softmax(t) overlapped
//    with S(t+1) MMAs inside each warp. 3-buffer (72KB) cp.async ring,
//    one cp group in flight, CTA = 4 warps / 64 Q rows, 3 CTAs/SM.
// ---------------------------------------------------------------------------
__global__ void __launch_bounds__(128, 3) attn_bf(const uint32_t* __restrict__ Qh,
                                                  const uint32_t* __restrict__ Ql,
                                                  const uint32_t* __restrict__ Kh,
                                                  const uint32_t* __restrict__ Kl,
                                                  const uint32_t* __restrict__ Vf,
                                                  uint32_t* __restrict__ O16) {
    extern __shared__ uint32_t sm[];
    const int tid = threadIdx.x, warp = tid >> 5, lane = tid & 31;
    const int g = lane >> 2, tq = lane & 3;
    const int bh = blockIdx.y, h = bh & 15;
    const uint32_t sbase = smem_u32(sm);

    uint4 qh_[4], ql_[4];
    {
        const size_t qb = ((size_t)(bh * 128 + blockIdx.x * 4 + warp)) * 4;
#pragma unroll
        for (int ks = 0; ks < 4; ks++) {
            qh_[ks] = *(const uint4*)(Qh + (qb + ks) * 128 + (g * 4 + tq) * 4);
            ql_[ks] = *(const uint4*)(Ql + (qb + ks) * 128 + (g * 4 + tq) * 4);
        }
    }

    const uint32_t* Kh0 = Kh + (size_t)bh * 65536;
    const uint32_t* Kl0 = Kl + (size_t)bh * 65536;
    const uint32_t* Vf0 = Vf + (size_t)bh * 65536;

    float oacc[8][4];
#pragma unroll
    for (int j = 0; j < 8; j++)
#pragma unroll
        for (int e = 0; e < 4; e++) oacc[j][e] = 0.f;
    float m0 = -1e30f, m1 = -1e30f, l0 = 0.f, l1 = 0.f;
    float sacc[8][4];

#define A_ISSUE(T, BUF) do {                                                  \
    const uint32_t sb_ = sbase + (uint32_t)(BUF) * 24576u;                    \
    _Pragma("unroll")                                                         \
    for (int i_ = 0; i_ < 4; i_++) {                                          \
        const int f_ = tid + i_ * 128;                                        \
        const size_t o_ = (size_t)(T) * 2048 + 4 * f_;                        \
        cpa16(sb_ + f_ * 16u,          Kh0 + o_);                             \
        cpa16(sb_ + 8192u + f_ * 16u,  Kl0 + o_);                             \
        cpa16(sb_ + 16384u + f_ * 16u, Vf0 + o_);                             \
    }                                                                         \
    cp_commit();                                                              \
} while (0)

// Compute S for tile in buffer BUF into sacc (96 fp16 MMAs).
#define S_COMPUTE(BUF) do {                                                          \
    const uint32_t* SKh_ = sm + (BUF) * 6144;                                        \
    const uint32_t* SKl_ = SKh_ + 2048;                                              \
    _Pragma("unroll")                                                                \
    for (int j_ = 0; j_ < 8; j_++)                                                   \
        _Pragma("unroll")                                                            \
        for (int e_ = 0; e_ < 4; e_++) sacc[j_][e_] = 0.f;                           \
    _Pragma("unroll")                                                                \
    for (int ks_ = 0; ks_ < 4; ks_++) {                                              \
        _Pragma("unroll")                                                            \
        for (int j_ = 0; j_ < 8; j_++) {                                             \
            const uint2 kbh_ = *(const uint2*)(SKh_ + (j_ * 4 + ks_) * 64 + (g * 4 + tq) * 2); \
            const uint2 kbl_ = *(const uint2*)(SKl_ + (j_ * 4 + ks_) * 64 + (g * 4 + tq) * 2); \
            mma_f16(sacc[j_], (const uint32_t*)&qh_[ks_], (const uint32_t*)&kbh_);   \
            mma_f16(sacc[j_], (const uint32_t*)&qh_[ks_], (const uint32_t*)&kbl_);   \
            mma_f16(sacc[j_], (const uint32_t*)&ql_[ks_], (const uint32_t*)&kbh_);   \
        }                                                                            \
    }                                                                                \
} while (0)

    const int NT = Sq / 64;
    // prologue: two loads in flight, then S(0)
    A_ISSUE(0, 0);
    A_ISSUE(1, 1);
    cp_wait<1>();
    __syncthreads();
    S_COMPUTE(0);

    for (int t = 0; t < NT; t++) {
        const int bufV = t % 3;
        if (t + 1 < NT) {
            cp_wait<0>();        // tile t+1 data complete
            __syncthreads();     // visible to all; also: all warps done with buf (t+2)%3's previous contents
        }
        if (t + 2 < NT) A_ISSUE(t + 2, (t + 2) % 3);

        // ---- softmax(t) on sacc -> pa (scalar; overlaps with S(t+1) MMAs below)
        float mx0 = -1e30f, mx1 = -1e30f;
#pragma unroll
        for (int j = 0; j < 8; j++) {
            mx0 = fmaxf(mx0, fmaxf(sacc[j][0], sacc[j][1]));
            mx1 = fmaxf(mx1, fmaxf(sacc[j][2], sacc[j][3]));
        }
        mx0 = fmaxf(mx0, __shfl_xor_sync(0xffffffffu, mx0, 1));
        mx0 = fmaxf(mx0, __shfl_xor_sync(0xffffffffu, mx0, 2));
        mx1 = fmaxf(mx1, __shfl_xor_sync(0xffffffffu, mx1, 1));
        mx1 = fmaxf(mx1, __shfl_xor_sync(0xffffffffu, mx1, 2));
        const float nm0 = fmaxf(m0, mx0), nm1 = fmaxf(m1, mx1);
        const float c0 = ex2(m0 - nm0), c1 = ex2(m1 - nm1);

        uint32_t pa[4][4];
        uint32_t pc0 = 0, pc1 = 0;
#pragma unroll
        for (int j = 0; j < 8; j++) {
            const uint32_t p0 = ex2h2(sacc[j][0] - nm0, sacc[j][1] - nm0);
            const uint32_t p1 = ex2h2(sacc[j][2] - nm1, sacc[j][3] - nm1);
            pc0 = hadd2u(pc0, p0);
            pc1 = hadd2u(pc1, p1);
            pa[j >> 1][(j & 1) * 2 + 0] = p0;
            pa[j >> 1][(j & 1) * 2 + 1] = p1;
        }
        const float2 f0 = h22f2(pc0), f1 = h22f2(pc1);
        float ls0 = f0.x + f0.y, ls1 = f1.x + f1.y;
        ls0 += __shfl_xor_sync(0xffffffffu, ls0, 1);
        ls0 += __shfl_xor_sync(0xffffffffu, ls0, 2);
        ls1 += __shfl_xor_sync(0xffffffffu, ls1, 1);
        ls1 += __shfl_xor_sync(0xffffffffu, ls1, 2);
        l0 = l0 * c0 + ls0; l1 = l1 * c1 + ls1;
        m0 = nm0; m1 = nm1;
#pragma unroll
        for (int j = 0; j < 8; j++) {
            oacc[j][0] *= c0; oacc[j][1] *= c0;
            oacc[j][2] *= c1; oacc[j][3] *= c1;
        }

        // ---- S(t+1) into sacc (tensor; scheduler interleaves with scalar above)
        if (t + 1 < NT) S_COMPUTE((t + 1) % 3);

        // ---- PV(t)
        {
            const uint32_t* SV = sm + bufV * 6144 + 4096;
#pragma unroll
            for (int ks = 0; ks < 4; ks++) {
#pragma unroll
                for (int j = 0; j < 8; j++) {
                    const uint2 vb = *(const uint2*)(SV + (ks * 8 + j) * 64 + (g * 4 + tq) * 2);
                    mma_f16(oacc[j], pa[ks], (const uint32_t*)&vb);
                }
            }
        }
    }
#undef A_ISSUE
#undef S_COMPUTE

    const float inv0 = 1.0f / l0, inv1 = 1.0f / l1;
    const int mt_o = (bh >> 4) * 128 + blockIdx.x * 4 + warp;
#pragma unroll
    for (int j = 0; j < 8; j++) {
        const size_t ix0 = ((size_t)(mt_o * 64 + h * 4 + (j >> 1))) * 128 + (g * 4 + tq) * 4 + 2 * (j & 1);
        O16[ix0]     = pkh2(oacc[j][0] * inv0, oacc[j][1] * inv0);
        O16[ix0 + 1] = pkh2(oacc[j][2] * inv1, oacc[j][3] * inv1);
    }
}

// ---------------------------------------------------------------------------
// Launcher
// ---------------------------------------------------------------------------
#define SMEM_64K 65536
#define SMEM_ATT 73728

extern "C" void kernel_launch(void* const* d_in, const int* in_sizes, int n_in,
                              void* d_out, int out_size) {
    const float* x    = (const float*)d_in[0];
    const float* ln_w = (const float*)d_in[1];
    const float* ln_b = (const float*)d_in[2];
    const float* Wq   = (const float*)d_in[3];
    const float* Wkv  = (const float*)d_in[4];
    const float* qg   = (const float*)d_in[5];
    const float* kg   = (const float*)d_in[6];
    const float* Wo   = (const float*)d_in[7];
    float* out = (float*)d_out;

    uint32_t *xnh, *xnl, *xn16, *wqkh, *wqkl, *wv16, *wo16;
    uint32_t *qfh, *qfl, *kfh, *kfl, *vf, *ao16;
    float *qk, *vbuf;
    cudaGetSymbolAddress((void**)&xnh,  g_xn_h);  cudaGetSymbolAddress((void**)&xnl,  g_xn_l);
    cudaGetSymbolAddress((void**)&xn16, g_xn16);
    cudaGetSymbolAddress((void**)&wqkh, g_wqk_h); cudaGetSymbolAddress((void**)&wqkl, g_wqk_l);
    cudaGetSymbolAddress((void**)&wv16, g_wv16);  cudaGetSymbolAddress((void**)&wo16, g_wo16);
    cudaGetSymbolAddress((void**)&qfh,  g_qf_h);  cudaGetSymbolAddress((void**)&qfl,  g_qf_l);
    cudaGetSymbolAddress((void**)&kfh,  g_kf_h);  cudaGetSymbolAddress((void**)&kfl,  g_kf_l);
    cudaGetSymbolAddress((void**)&vf,   g_vf);    cudaGetSymbolAddress((void**)&ao16, g_ao16);
    cudaGetSymbolAddress((void**)&qk,   g_qk);    cudaGetSymbolAddress((void**)&vbuf, g_v);

    cudaFuncSetAttribute(proj_fused, cudaFuncAttributeMaxDynamicSharedMemorySize, SMEM_64K);
    cudaFuncSetAttribute(gemm_f16s,  cudaFuncAttributeMaxDynamicSharedMemorySize, SMEM_64K);
    cudaFuncSetAttribute(attn_bf,    cudaFuncAttributeMaxDynamicSharedMemorySize, SMEM_ATT);

    // prep: LN (4096) + Wq (2048) + Wkv (4096) + Wo (2048)
    prep_kernel<<<TOK + 8192, 256>>>(x, ln_w, ln_b, xnh, xnl, xn16,
                                     Wq, Wkv, Wo, wqkh, wqkl, wv16, wo16);

    // fused QK (bf16x3) + V (fp16) projections in one launch
    proj_fused<<<dim3(24, TOK / 128), 256, SMEM_64K>>>(xnh, xnl, xn16,
                                                       wqkh, wqkl, wv16, qk, vbuf);

    rms_kernel<<<TOK / 2, 256>>>(qk, vbuf, qg, kg, qfh, qfl, kfh, kfl, vf);

    attn_bf<<<dim3(Sq / 64, Bz * Hn), 128, SMEM_ATT>>>(qfh, qfl, kfh, kfl, vf, ao16);

    // output projection (fp16 single)
    gemm_f16s<<<dim3(DIM / 128, TOK / 128), 256, SMEM_64K>>>(ao16, wo16, out, DIM, INNER);
}

// round 12
// speedup vs baseline: 1.0454x; 1.0454x over previous
#include <cuda_runtime.h>
#include <cuda_bf16.h>
#include <cuda_fp16.h>
#include <cstdint>

#define Bz    2
#define Sq    2048
#define DIM   1024
#define Hn    16
#define DHd   64
#define INNER 1024
#define TOK   4096

// ---------------------------------------------------------------------------
// Scratch (device globals). Fragment arrays are uint32 (packed 16-bit x2).
// ---------------------------------------------------------------------------
__device__ uint32_t g_xn_h[TOK*DIM/2],     g_xn_l[TOK*DIM/2];   // bf16 hi/lo A-frags
__device__ uint32_t g_xn16[TOK*DIM/2];                          // fp16 single A-frags
__device__ uint32_t g_wqk_h[DIM*2048/2],   g_wqk_l[DIM*2048/2]; // Wq|Wk bf16 B-frags
__device__ uint32_t g_wv16[DIM*INNER/2];                        // Wv fp16 B-frags
__device__ uint32_t g_wo16[INNER*DIM/2];                        // Wo fp16 B-frags
__device__ float    g_qk[TOK*2048];                             // q|k projection (fp32)
__device__ float    g_v [TOK*INNER];                            // v projection (fp32)
__device__ uint32_t g_qf_h[TOK*INNER/2],   g_qf_l[TOK*INNER/2]; // fp16 hi/lo
__device__ uint32_t g_kf_h[TOK*INNER/2],   g_kf_l[TOK*INNER/2]; // fp16 hi/lo
__device__ uint32_t g_vf  [TOK*INNER/2];                        // fp16 single
__device__ uint32_t g_ao16[TOK*INNER/2];                        // attn out fp16 A-frags

// ---------------------------------------------------------------------------
// Helpers
// ---------------------------------------------------------------------------
__device__ __forceinline__ uint32_t smem_u32(const void* p) {
    uint32_t a;
    asm("{ .reg .u64 t; cvta.to.shared.u64 t, %1; cvt.u32.u64 %0, t; }" : "=r"(a) : "l"(p));
    return a;
}
__device__ __forceinline__ uint32_t pkbf(float a, float b) {
    return (uint32_t)__bfloat16_as_ushort(__float2bfloat16_rn(a)) |
           ((uint32_t)__bfloat16_as_ushort(__float2bfloat16_rn(b)) << 16);
}
__device__ __forceinline__ void splitbf(float a, float b, uint32_t& hi, uint32_t& lo) {
    __nv_bfloat16 ha = __float2bfloat16_rn(a), hb = __float2bfloat16_rn(b);
    hi = (uint32_t)__bfloat16_as_ushort(ha) | ((uint32_t)__bfloat16_as_ushort(hb) << 16);
    lo = pkbf(a - __bfloat162float(ha), b - __bfloat162float(hb));
}
__device__ __forceinline__ uint32_t pkh2(float a, float b) {
    __half2 h = __floats2half2_rn(a, b);
    return *(uint32_t*)&h;
}
__device__ __forceinline__ void splitf16(float a, float b, uint32_t& hi, uint32_t& lo) {
    __half ha = __float2half_rn(a), hb = __float2half_rn(b);
    __half2 hp = __halves2half2(ha, hb);
    hi = *(uint32_t*)&hp;
    lo = pkh2(a - __half2float(ha), b - __half2float(hb));
}
__device__ __forceinline__ float ex2(float x) {
    float y;
    asm("ex2.approx.f32 %0, %1;" : "=f"(y) : "f"(x));
    return y;
}
// exp2 of two fp32 values -> packed fp16x2 {lo=exp2(a), hi=exp2(b)}
__device__ __forceinline__ uint32_t ex2h2(float a, float b) {
    uint32_t r;
    asm("{ .reg .b32 t; cvt.rn.f16x2.f32 t, %2, %1; ex2.approx.f16x2 %0, t; }"
        : "=r"(r) : "f"(a), "f"(b));
    return r;
}
__device__ __forceinline__ uint32_t hadd2u(uint32_t a, uint32_t b) {
    uint32_t r;
    asm("add.f16x2 %0, %1, %2;" : "=r"(r) : "r"(a), "r"(b));
    return r;
}
__device__ __forceinline__ float2 h22f2(uint32_t h) {
    __half2 hh = *(__half2*)&h;
    return __half22float2(hh);
}
__device__ __forceinline__ void mma_bf(float* c, const uint32_t* a, const uint32_t* b) {
    asm volatile(
        "mma.sync.aligned.m16n8k16.row.col.f32.bf16.bf16.f32 "
        "{%0,%1,%2,%3}, {%4,%5,%6,%7}, {%8,%9}, {%0,%1,%2,%3};"
        : "+f"(c[0]), "+f"(c[1]), "+f"(c[2]), "+f"(c[3])
        : "r"(a[0]), "r"(a[1]), "r"(a[2]), "r"(a[3]), "r"(b[0]), "r"(b[1]));
}
__device__ __forceinline__ void mma_f16(float* c, const uint32_t* a, const uint32_t* b) {
    asm volatile(
        "mma.sync.aligned.m16n8k16.row.col.f32.f16.f16.f32 "
        "{%0,%1,%2,%3}, {%4,%5,%6,%7}, {%8,%9}, {%0,%1,%2,%3};"
        : "+f"(c[0]), "+f"(c[1]), "+f"(c[2]), "+f"(c[3])
        : "r"(a[0]), "r"(a[1]), "r"(a[2]), "r"(a[3]), "r"(b[0]), "r"(b[1]));
}
__device__ __forceinline__ void cpa16(uint32_t saddr, const void* gptr) {
    asm volatile("cp.async.cg.shared.global [%0], [%1], 16;" :: "r"(saddr), "l"(gptr) : "memory");
}
__device__ __forceinline__ void cp_commit() { asm volatile("cp.async.commit_group;" ::: "memory"); }
template <int N> __device__ __forceinline__ void cp_wait() {
    asm volatile("cp.async.wait_group %0;" :: "n"(N) : "memory");
}

// ---------------------------------------------------------------------------
// 1) Prep: blocks [0,4096) LayerNorm; [4096,5120) coalesced weight frags.
//    Weight blocks: matrix = r/256 (0=Wq,1=Wk,2=Wv,3=Wo). Warp handles one
//    (pb, nt0..nt0+3) chunk group: 16 coalesced row reads, 2 uint4 stores/lane.
// ---------------------------------------------------------------------------
__global__ void __launch_bounds__(256) prep_kernel(const float* __restrict__ x,
                                                   const float* __restrict__ w,
                                                   const float* __restrict__ bias,
                                                   uint32_t* __restrict__ xh,
                                                   uint32_t* __restrict__ xl,
                                                   uint32_t* __restrict__ x16,
                                                   const float* __restrict__ Wq,
                                                   const float* __restrict__ Wkv,
                                                   const float* __restrict__ Wo,
                                                   uint32_t* __restrict__ wqkh,
                                                   uint32_t* __restrict__ wqkl,
                                                   uint32_t* __restrict__ wv16,
                                                   uint32_t* __restrict__ wo16) {
    const int bid = blockIdx.x;
    if (bid >= TOK) {
        const int r = bid - TOK;               // [0,1024)
        const int mat = r >> 8;                // 0=Wq 1=Wk 2=Wv 3=Wo
        const int warp = threadIdx.x >> 5, lane = threadIdx.x & 31;
        const int gw = (r & 255) * 8 + warp;   // [0,2048)
        const int pb  = gw & 63;               // K/16 block (KS=64)
        const int nt0 = (gw >> 6) << 2;        // 4 nt per warp
        const int ntl = lane >> 3, g = lane & 7;
        const int nt  = nt0 + ntl;
        const int n_local = nt * 8 + g;

        const float* src;
        int stride, col;
        if (mat == 0)      { src = Wq;  stride = 1024; col = n_local; }
        else if (mat == 1) { src = Wkv; stride = 2048; col = n_local; }
        else if (mat == 2) { src = Wkv; stride = 2048; col = 1024 + n_local; }
        else               { src = Wo;  stride = 1024; col = n_local; }

        float v[16];
#pragma unroll
        for (int i = 0; i < 16; i++)
            v[i] = src[(size_t)(16 * pb + i) * stride + col];

        if (mat <= 1) {
            // bf16 hi/lo
            uint32_t hiw[8], low[8];
#pragma unroll
            for (int o = 0; o < 8; o++) {
                const int pl = ((o & 1) << 2) + (o >> 1);     // p within block
                splitbf(v[2 * pl], v[2 * pl + 1], hiw[o], low[o]);
            }
            const int out_nt = (mat == 0 ? 0 : 128) + nt;
            const size_t base = ((size_t)(out_nt * 64 + pb)) * 64 + g * 8;
            *(uint4*)(wqkh + base)     = make_uint4(hiw[0], hiw[1], hiw[2], hiw[3]);
            *(uint4*)(wqkh + base + 4) = make_uint4(hiw[4], hiw[5], hiw[6], hiw[7]);
            *(uint4*)(wqkl + base)     = make_uint4(low[0], low[1], low[2], low[3]);
            *(uint4*)(wqkl + base + 4) = make_uint4(low[4], low[5], low[6], low[7]);
        } else {
            // fp16 single
            uint32_t wd[8];
#pragma unroll
            for (int o = 0; o < 8; o++) {
                const int pl = ((o & 1) << 2) + (o >> 1);
                wd[o] = pkh2(v[2 * pl], v[2 * pl + 1]);
            }
            uint32_t* dst = (mat == 2) ? wv16 : wo16;
            const size_t base = ((size_t)(nt * 64 + pb)) * 64 + g * 8;
            *(uint4*)(dst + base)     = make_uint4(wd[0], wd[1], wd[2], wd[3]);
            *(uint4*)(dst + base + 4) = make_uint4(wd[4], wd[5], wd[6], wd[7]);
        }
        return;
    }
    const int row = bid;
    const float* xr = x + (size_t)row * DIM;
    float2 v[2];
    v[0] = *(const float2*)(xr + 2 * threadIdx.x);
    v[1] = *(const float2*)(xr + 2 * (threadIdx.x + 256));
    float s  = v[0].x + v[0].y + v[1].x + v[1].y;
    float sq = v[0].x * v[0].x + v[0].y * v[0].y + v[1].x * v[1].x + v[1].y * v[1].y;
#pragma unroll
    for (int off = 16; off; off >>= 1) {
        s  += __shfl_xor_sync(0xffffffffu, s, off);
        sq += __shfl_xor_sync(0xffffffffu, sq, off);
    }
    __shared__ float red[2][8];
    const int warp = threadIdx.x >> 5, lane = threadIdx.x & 31;
    if (lane == 0) { red[0][warp] = s; red[1][warp] = sq; }
    __syncthreads();
    float ts = 0.f, tq2 = 0.f;
#pragma unroll
    for (int i = 0; i < 8; i++) { ts += red[0][i]; tq2 += red[1][i]; }
    const float mean = ts * (1.0f / DIM);
    const float var  = tq2 * (1.0f / DIM) - mean * mean;
    const float rstd = rsqrtf(var + 1e-5f);
    const int mt = row >> 4, mr = row & 15, g = mr & 7, hih = mr >> 3;
#pragma unroll
    for (int i = 0; i < 2; i++) {
        const int p = threadIdx.x + i * 256;
        const float2 wv = *(const float2*)(w + 2 * p);
        const float2 bv = *(const float2*)(bias + 2 * p);
        const float y0 = wv.x * (v[i].x - mean) * rstd + bv.x;
        const float y1 = wv.y * (v[i].y - mean) * rstd + bv.y;
        const int ks = p >> 3, c = p & 7, tq = c & 3, ch = c >> 2;
        const size_t idx = ((size_t)(mt * 64 + ks)) * 128 + (g * 4 + tq) * 4 + hih + 2 * ch;
        uint32_t hi, lo;
        splitbf(y0, y1, hi, lo);
        xh[idx] = hi; xl[idx] = lo;
        x16[idx] = pkh2(y0, y1);
    }
}

// ---------------------------------------------------------------------------
// 2a) bf16x3 GEMM body: 128x128 tile, BK=32, 2-stage cp.async.
// ---------------------------------------------------------------------------
__device__ __forceinline__ void gemm_bf3_body(const uint32_t* __restrict__ Ah,
                                              const uint32_t* __restrict__ Al,
                                              const uint32_t* __restrict__ Bh,
                                              const uint32_t* __restrict__ Bl,
                                              float* __restrict__ C,
                                              int N, int K, int bm, int bn,
                                              uint32_t* sm) {
    const int tid = threadIdx.x, wid = tid >> 5, lane = tid & 31;
    const int wr = wid >> 2, wc = wid & 3, g = lane >> 2, tq = lane & 3;
    const int KS = K >> 4, NSTG = K >> 5;
    const uint32_t sbase = smem_u32(sm);

    const uint32_t* Ah0 = Ah + (size_t)(bm >> 4) * KS * 128;
    const uint32_t* Al0 = Al + (size_t)(bm >> 4) * KS * 128;
    const uint32_t* Bh0 = Bh + (size_t)(bn >> 3) * KS * 64;
    const uint32_t* Bl0 = Bl + (size_t)(bn >> 3) * KS * 64;

    float acc[4][4][4];
#pragma unroll
    for (int i = 0; i < 4; i++)
#pragma unroll
        for (int j = 0; j < 4; j++)
#pragma unroll
            for (int e = 0; e < 4; e++) acc[i][j][e] = 0.f;

#define G_ISSUE(S, BUF) do {                                                        \
    const uint32_t sb_ = sbase + (uint32_t)(BUF) * 32768u;                          \
    _Pragma("unroll")                                                               \
    for (int i_ = 0; i_ < 2; i_++) {                                                \
        const int f_ = tid + i_ * 256;                                              \
        const int mt_ = f_ >> 6, wA_ = (4 * f_) & 255;                              \
        const int ksA_ = wA_ >> 7, frA_ = wA_ & 127;                                \
        const size_t oa_ = ((size_t)mt_ * KS + (S) * 2 + ksA_) * 128 + frA_;        \
        cpa16(sb_ + f_ * 16u,           Ah0 + oa_);                                 \
        cpa16(sb_ + 8192u + f_ * 16u,   Al0 + oa_);                                 \
        const int nt_ = f_ >> 5, wB_ = (4 * f_) & 127;                              \
        const int ksB_ = wB_ >> 6, frB_ = wB_ & 63;                                 \
        const size_t ob_ = ((size_t)nt_ * KS + (S) * 2 + ksB_) * 64 + frB_;         \
        cpa16(sb_ + 16384u + f_ * 16u,  Bh0 + ob_);                                 \
        cpa16(sb_ + 24576u + f_ * 16u,  Bl0 + ob_);                                 \
    }                                                                               \
    cp_commit();                                                                    \
} while (0)

    G_ISSUE(0, 0);
    int buf = 0;
    for (int s = 0; s < NSTG; s++) {
        if (s + 1 < NSTG) { G_ISSUE(s + 1, buf ^ 1); cp_wait<1>(); }
        else              { cp_wait<0>(); }
        __syncthreads();
        const uint32_t* S0 = sm + buf * 8192;
#pragma unroll
        for (int ksl = 0; ksl < 2; ksl++) {
            uint4 ah[4], al[4];
            uint2 bh[4], bl[4];
#pragma unroll
            for (int i = 0; i < 4; i++) {
                const int mt = wr * 4 + i;
                ah[i] = *(const uint4*)(S0 + (mt * 2 + ksl) * 128 + (g * 4 + tq) * 4);
                al[i] = *(const uint4*)(S0 + 2048 + (mt * 2 + ksl) * 128 + (g * 4 + tq) * 4);
            }
#pragma unroll
            for (int j = 0; j < 4; j++) {
                const int nt = wc * 4 + j;
                bh[j] = *(const uint2*)(S0 + 4096 + (nt * 2 + ksl) * 64 + (g * 4 + tq) * 2);
                bl[j] = *(const uint2*)(S0 + 6144 + (nt * 2 + ksl) * 64 + (g * 4 + tq) * 2);
            }
#pragma unroll
            for (int i = 0; i < 4; i++)
#pragma unroll
                for (int j = 0; j < 4; j++) {
                    mma_bf(acc[i][j], (const uint32_t*)&ah[i], (const uint32_t*)&bh[j]);
                    mma_bf(acc[i][j], (const uint32_t*)&ah[i], (const uint32_t*)&bl[j]);
                    mma_bf(acc[i][j], (const uint32_t*)&al[i], (const uint32_t*)&bh[j]);
                }
        }
        __syncthreads();
        buf ^= 1;
    }
#undef G_ISSUE

#pragma unroll
    for (int i = 0; i < 4; i++) {
        const int r0 = bm + (wr * 4 + i) * 16 + g;
#pragma unroll
        for (int j = 0; j < 4; j++) {
            const int c0 = bn + (wc * 4 + j) * 8 + 2 * tq;
            *(float2*)(C + (size_t)r0 * N + c0)       = make_float2(acc[i][j][0], acc[i][j][1]);
            *(float2*)(C + (size_t)(r0 + 8) * N + c0) = make_float2(acc[i][j][2], acc[i][j][3]);
        }
    }
}

// ---------------------------------------------------------------------------
// 2b) fp16-single GEMM body: 128x128 tile, BK=64, 2-stage cp.async, 1 MMA.
// ---------------------------------------------------------------------------
__device__ __forceinline__ void gemm_f16s_body(const uint32_t* __restrict__ Af,
                                               const uint32_t* __restrict__ Bf,
                                               float* __restrict__ C,
                                               int N, int K, int bm, int bn,
                                               uint32_t* sm) {
    const int tid = threadIdx.x, wid = tid >> 5, lane = tid & 31;
    const int wr = wid >> 2, wc = wid & 3, g = lane >> 2, tq = lane & 3;
    const int KS = K >> 4, NSTG = K >> 6;
    const uint32_t sbase = smem_u32(sm);

    const uint32_t* A0g = Af + (size_t)(bm >> 4) * KS * 128;
    const uint32_t* B0g = Bf + (size_t)(bn >> 3) * KS * 64;

    float acc[4][4][4];
#pragma unroll
    for (int i = 0; i < 4; i++)
#pragma unroll
        for (int j = 0; j < 4; j++)
#pragma unroll
            for (int e = 0; e < 4; e++) acc[i][j][e] = 0.f;

#define F_ISSUE(S, BUF) do {                                                        \
    const uint32_t sb_ = sbase + (uint32_t)(BUF) * 32768u;                          \
    _Pragma("unroll")                                                               \
    for (int i_ = 0; i_ < 4; i_++) {                                                \
        const int f_ = tid + i_ * 256;                                              \
        const int mt_ = f_ >> 7, wA_ = (4 * f_) & 511;                              \
        const int ksA_ = wA_ >> 7, frA_ = wA_ & 127;                                \
        const size_t oa_ = ((size_t)mt_ * KS + (S) * 4 + ksA_) * 128 + frA_;        \
        cpa16(sb_ + f_ * 16u, A0g + oa_);                                           \
        const int nt_ = f_ >> 6, wB_ = (4 * f_) & 255;                              \
        const int ksB_ = wB_ >> 6, frB_ = wB_ & 63;                                 \
        const size_t ob_ = ((size_t)nt_ * KS + (S) * 4 + ksB_) * 64 + frB_;         \
        cpa16(sb_ + 16384u + f_ * 16u, B0g + ob_);                                  \
    }                                                                               \
    cp_commit();                                                                    \
} while (0)

    F_ISSUE(0, 0);
    int buf = 0;
    for (int s = 0; s < NSTG; s++) {
        if (s + 1 < NSTG) { F_ISSUE(s + 1, buf ^ 1); cp_wait<1>(); }
        else              { cp_wait<0>(); }
        __syncthreads();
        const uint32_t* S0 = sm + buf * 8192;
#pragma unroll
        for (int ksl = 0; ksl < 4; ksl++) {
            uint4 a[4];
            uint2 b[4];
#pragma unroll
            for (int i = 0; i < 4; i++)
                a[i] = *(const uint4*)(S0 + ((wr * 4 + i) * 4 + ksl) * 128 + (g * 4 + tq) * 4);
#pragma unroll
            for (int j = 0; j < 4; j++)
                b[j] = *(const uint2*)(S0 + 4096 + ((wc * 4 + j) * 4 + ksl) * 64 + (g * 4 + tq) * 2);
#pragma unroll
            for (int i = 0; i < 4; i++)
#pragma unroll
                for (int j = 0; j < 4; j++)
                    mma_f16(acc[i][j], (const uint32_t*)&a[i], (const uint32_t*)&b[j]);
        }
        __syncthreads();
        buf ^= 1;
    }
#undef F_ISSUE

#pragma unroll
    for (int i = 0; i < 4; i++) {
        const int r0 = bm + (wr * 4 + i) * 16 + g;
#pragma unroll
        for (int j = 0; j < 4; j++) {
            const int c0 = bn + (wc * 4 + j) * 8 + 2 * tq;
            *(float2*)(C + (size_t)r0 * N + c0)       = make_float2(acc[i][j][0], acc[i][j][1]);
            *(float2*)(C + (size_t)(r0 + 8) * N + c0) = make_float2(acc[i][j][2], acc[i][j][3]);
        }
    }
}

// Fused QK (bf16x3) + V (fp16) projection: grid (24, 32).
__global__ void __launch_bounds__(256, 2) proj_fused(const uint32_t* __restrict__ xh,
                                                     const uint32_t* __restrict__ xl,
                                                     const uint32_t* __restrict__ x16,
                                                     const uint32_t* __restrict__ wqkh,
                                                     const uint32_t* __restrict__ wqkl,
                                                     const uint32_t* __restrict__ wv16,
                                                     float* __restrict__ qk,
                                                     float* __restrict__ v) {
    extern __shared__ uint32_t sm[];
    if (blockIdx.x < 16)
        gemm_bf3_body(xh, xl, wqkh, wqkl, qk, 2048, 1024,
                      blockIdx.y * 128, blockIdx.x * 128, sm);
    else
        gemm_f16s_body(x16, wv16, v, 1024, 1024,
                       blockIdx.y * 128, (blockIdx.x - 16) * 128, sm);
}

// Standalone fp16-single GEMM (output projection).
__global__ void __launch_bounds__(256, 2) gemm_f16s(const uint32_t* __restrict__ Af,
                                                    const uint32_t* __restrict__ Bf,
                                                    float* __restrict__ C,
                                                    int N, int K) {
    extern __shared__ uint32_t sm[];
    gemm_f16s_body(Af, Bf, C, N, K, blockIdx.y * 128, blockIdx.x * 128, sm);
}

// ---------------------------------------------------------------------------
// 3) RMSNorm + head-split: Q, K -> fp16 hi/lo frags; V -> single fp16 B-frags.
// ---------------------------------------------------------------------------
#define LOG2E 1.4426950408889634f

__global__ void __launch_bounds__(256) rms_kernel(const float* __restrict__ qk,
                                                  const float* __restrict__ vv,
                                                  const float* __restrict__ qg,
                                                  const float* __restrict__ kg,
                                                  uint32_t* __restrict__ qfh, uint32_t* __restrict__ qfl,
                                                  uint32_t* __restrict__ kfh, uint32_t* __restrict__ kfl,
                                                  uint32_t* __restrict__ vf) {
    const int tk0 = blockIdx.x * 2;
    const int warp = threadIdx.x >> 5, lane = threadIdx.x & 31;
    const int b = tk0 >> 11, s0 = tk0 & 2047;
    const int ks = lane >> 3, c = lane & 7, tq = c & 3, ch = c >> 2;
#pragma unroll
    for (int i = 0; i < 2; i++) {
        const int h = warp * 2 + i;
        const int bh = b * 16 + h;
        const float2 gq = *(const float2*)(qg + h * 64 + 2 * lane);
        const float2 gk = *(const float2*)(kg + h * 64 + 2 * lane);
#pragma unroll
        for (int tt = 0; tt < 2; tt++) {
            const int token = tk0 + tt, s = s0 + tt;
            {
                const float2 qv = *(const float2*)(qk + (size_t)token * 2048 + h * 64 + 2 * lane);
                float ss = qv.x * qv.x + qv.y * qv.y;
#pragma unroll
                for (int off = 16; off; off >>= 1) ss += __shfl_xor_sync(0xffffffffu, ss, off);
                const float r = rsqrtf(ss * (1.0f / DHd) + 1e-8f) * (8.0f * LOG2E);
                const int mt = s >> 4, mr = s & 15, gg = mr & 7, hih = mr >> 3;
                const size_t qi = ((size_t)(bh * 128 + mt) * 4 + ks) * 128 + (gg * 4 + tq) * 4 + hih + 2 * ch;
                uint32_t hi, lo;
                splitf16(qv.x * r * gq.x, qv.y * r * gq.y, hi, lo);
                qfh[qi] = hi; qfl[qi] = lo;
            }
            {
                const float2 kvv = *(const float2*)(qk + (size_t)token * 2048 + 1024 + h * 64 + 2 * lane);
                float ss = kvv.x * kvv.x + kvv.y * kvv.y;
#pragma unroll
                for (int off = 16; off; off >>= 1) ss += __shfl_xor_sync(0xffffffffu, ss, off);
                const float r = rsqrtf(ss * (1.0f / DHd) + 1e-8f) * 8.0f;
                const int nt = s >> 3, gg = s & 7;
                const size_t ki = ((size_t)(bh * 256 + nt) * 4 + ks) * 64 + (gg * 4 + tq) * 2 + ch;
                uint32_t hi, lo;
                splitf16(kvv.x * r * gk.x, kvv.y * r * gk.y, hi, lo);
                kfh[ki] = hi; kfl[ki] = lo;
            }
        }
        {
            const float2 va = *(const float2*)(vv + (size_t)tk0 * 1024 + h * 64 + 2 * lane);
            const float2 vb = *(const float2*)(vv + (size_t)(tk0 + 1) * 1024 + h * 64 + 2 * lane);
            const int pq = s0 >> 1;
            const int ksv = pq >> 3, cv = pq & 7, tv = cv & 3, rv = cv >> 2;
            const int d0 = 2 * lane;
            const size_t vi0 = ((size_t)(bh * 128 + ksv) * 8 + (d0 >> 3)) * 64 + ((d0 & 7) * 4 + tv) * 2 + rv;
            const size_t vi1 = ((size_t)(bh * 128 + ksv) * 8 + ((d0 + 1) >> 3)) * 64 + (((d0 + 1) & 7) * 4 + tv) * 2 + rv;
            vf[vi0] = pkh2(va.x, vb.x);
            vf[vi1] = pkh2(va.y, vb.y);
        }
    }
}

// ---------------------------------------------------------------------------
// 4) Flash attention (R10 structure), fp16 MMA, f16x2 exp softmax, rescale
//    skipped (bit-exact) when no row max in the warp updated this tile.
//    CTA = 4 warps / 64 Q rows, 2-stage 48KB pipeline -> 4 CTAs/SM.
// ---------------------------------------------------------------------------
__global__ void __launch_bounds__(128, 4) attn_bf(const uint32_t* __restrict__ Qh,
                                                  const uint32_t* __restrict__ Ql,
                                                  const uint32_t* __restrict__ Kh,
                                                  const uint32_t* __restrict__ Kl,
                                                  const uint32_t* __restrict__ Vf,
                                                  uint32_t* __restrict__ O16) {
    extern __shared__ uint32_t sm[];
    const int tid = threadIdx.x, warp = tid >> 5, lane = tid & 31;
    const int g = lane >> 2, tq = lane & 3;
    const int bh = blockIdx.y, h = bh & 15;
    const uint32_t sbase = smem_u32(sm);

    uint4 qh_[4], ql_[4];
    {
        const size_t qb = ((size_t)(bh * 128 + blockIdx.x * 4 + warp)) * 4;
#pragma unroll
        for (int ks = 0; ks < 4; ks++) {
            qh_[ks] = *(const uint4*)(Qh + (qb + ks) * 128 + (g * 4 + tq) * 4);
            ql_[ks] = *(const uint4*)(Ql + (qb + ks) * 128 + (g * 4 + tq) * 4);
        }
    }

    const uint32_t* Kh0 = Kh + (size_t)bh * 65536;
    const uint32_t* Kl0 = Kl + (size_t)bh * 65536;
    const uint32_t* Vf0 = Vf + (size_t)bh * 65536;

    float oacc[8][4];
#pragma unroll
    for (int j = 0; j < 8; j++)
#pragma unroll
        for (int e = 0; e < 4; e++) oacc[j][e] = 0.f;
    float m0 = -1e30f, m1 = -1e30f, l0 = 0.f, l1 = 0.f;

#define A_ISSUE(T, BUF) do {                                                  \
    const uint32_t sb_ = sbase + (uint32_t)(BUF) * 24576u;                    \
    _Pragma("unroll")                                                         \
    for (int i_ = 0; i_ < 4; i_++) {                                          \
        const int f_ = tid + i_ * 128;                                        \
        const size_t o_ = (size_t)(T) * 2048 + 4 * f_;                        \
        cpa16(sb_ + f_ * 16u,          Kh0 + o_);                             \
        cpa16(sb_ + 8192u + f_ * 16u,  Kl0 + o_);                             \
        cpa16(sb_ + 16384u + f_ * 16u, Vf0 + o_);                             \
    }                                                                         \
    cp_commit();                                                              \
} while (0)

    A_ISSUE(0, 0);
    int buf = 0;
    const int NT = Sq / 64;
    for (int t = 0; t < NT; t++) {
        if (t + 1 < NT) { A_ISSUE(t + 1, buf ^ 1); cp_wait<1>(); }
        else            { cp_wait<0>(); }
        __syncthreads();
        const uint32_t* SKh = sm + buf * 6144;
        const uint32_t* SKl = SKh + 2048;
        const uint32_t* SV  = SKh + 4096;

        float sacc[8][4];
#pragma unroll
        for (int j = 0; j < 8; j++)
#pragma unroll
            for (int e = 0; e < 4; e++) sacc[j][e] = 0.f;
#pragma unroll
        for (int ks = 0; ks < 4; ks++) {
#pragma unroll
            for (int j = 0; j < 8; j++) {
                const uint2 kbh = *(const uint2*)(SKh + (j * 4 + ks) * 64 + (g * 4 + tq) * 2);
                const uint2 kbl = *(const uint2*)(SKl + (j * 4 + ks) * 64 + (g * 4 + tq) * 2);
                mma_f16(sacc[j], (const uint32_t*)&qh_[ks], (const uint32_t*)&kbh);
                mma_f16(sacc[j], (const uint32_t*)&qh_[ks], (const uint32_t*)&kbl);
                mma_f16(sacc[j], (const uint32_t*)&ql_[ks], (const uint32_t*)&kbh);
            }
        }

        float mx0 = -1e30f, mx1 = -1e30f;
#pragma unroll
        for (int j = 0; j < 8; j++) {
            mx0 = fmaxf(mx0, fmaxf(sacc[j][0], sacc[j][1]));
            mx1 = fmaxf(mx1, fmaxf(sacc[j][2], sacc[j][3]));
        }
        mx0 = fmaxf(mx0, __shfl_xor_sync(0xffffffffu, mx0, 1));
        mx0 = fmaxf(mx0, __shfl_xor_sync(0xffffffffu, mx0, 2));
        mx1 = fmaxf(mx1, __shfl_xor_sync(0xffffffffu, mx1, 1));
        mx1 = fmaxf(mx1, __shfl_xor_sync(0xffffffffu, mx1, 2));
        const float nm0 = fmaxf(m0, mx0), nm1 = fmaxf(m1, mx1);

        // Rescale only if ANY lane's row max changed (bit-exact skip: c==1).
        const bool upd = (nm0 != m0) || (nm1 != m1);
        if (__any_sync(0xffffffffu, upd)) {
            const float c0 = ex2(m0 - nm0), c1 = ex2(m1 - nm1);
            l0 *= c0; l1 *= c1;
#pragma unroll
            for (int j = 0; j < 8; j++) {
                oacc[j][0] *= c0; oacc[j][1] *= c0;
                oacc[j][2] *= c1; oacc[j][3] *= c1;
            }
            m0 = nm0; m1 = nm1;
        }

        // exp via f16x2 MUFU; result pairs ARE the fp16 P fragments.
        uint32_t pa[4][4];
        uint32_t pc0 = 0, pc1 = 0;
#pragma unroll
        for (int j = 0; j < 8; j++) {
            const uint32_t p0 = ex2h2(sacc[j][0] - m0, sacc[j][1] - m0);
            const uint32_t p1 = ex2h2(sacc[j][2] - m1, sacc[j][3] - m1);
            pc0 = hadd2u(pc0, p0);
            pc1 = hadd2u(pc1, p1);
            pa[j >> 1][(j & 1) * 2 + 0] = p0;
            pa[j >> 1][(j & 1) * 2 + 1] = p1;
        }
        const float2 f0 = h22f2(pc0), f1 = h22f2(pc1);
        float ls0 = f0.x + f0.y, ls1 = f1.x + f1.y;
        ls0 += __shfl_xor_sync(0xffffffffu, ls0, 1);
        ls0 += __shfl_xor_sync(0xffffffffu, ls0, 2);
        ls1 += __shfl_xor_sync(0xffffffffu, ls1, 1);
        ls1 += __shfl_xor_sync(0xffffffffu, ls1, 2);
        l0 += ls0; l1 += ls1;

#pragma unroll
        for (int ks = 0; ks < 4; ks++) {
#pragma unroll
            for (int j = 0; j < 8; j++) {
                const uint2 vb = *(const uint2*)(SV + (ks * 8 + j) * 64 + (g * 4 + tq) * 2);
                mma_f16(oacc[j], pa[ks], (const uint32_t*)&vb);
            }
        }
        __syncthreads();
        buf ^= 1;
    }
#undef A_ISSUE

    const float inv0 = 1.0f / l0, inv1 = 1.0f / l1;
    const int mt_o = (bh >> 4) * 128 + blockIdx.x * 4 + warp;
#pragma unroll
    for (int j = 0; j < 8; j++) {
        const size_t ix0 = ((size_t)(mt_o * 64 + h * 4 + (j >> 1))) * 128 + (g * 4 + tq) * 4 + 2 * (j & 1);
        O16[ix0]     = pkh2(oacc[j][0] * inv0, oacc[j][1] * inv0);
        O16[ix0 + 1] = pkh2(oacc[j][2] * inv1, oacc[j][3] * inv1);
    }
}

// ---------------------------------------------------------------------------
// Launcher
// ---------------------------------------------------------------------------
#define SMEM_64K 65536
#define SMEM_ATT 49152

extern "C" void kernel_launch(void* const* d_in, const int* in_sizes, int n_in,
                              void* d_out, int out_size) {
    const float* x    = (const float*)d_in[0];
    const float* ln_w = (const float*)d_in[1];
    const float* ln_b = (const float*)d_in[2];
    const float* Wq   = (const float*)d_in[3];
    const float* Wkv  = (const float*)d_in[4];
    const float* qg   = (const float*)d_in[5];
    const float* kg   = (const float*)d_in[6];
    const float* Wo   = (const float*)d_in[7];
    float* out = (float*)d_out;

    uint32_t *xnh, *xnl, *xn16, *wqkh, *wqkl, *wv16, *wo16;
    uint32_t *qfh, *qfl, *kfh, *kfl, *vf, *ao16;
    float *qk, *vbuf;
    cudaGetSymbolAddress((void**)&xnh,  g_xn_h);  cudaGetSymbolAddress((void**)&xnl,  g_xn_l);
    cudaGetSymbolAddress((void**)&xn16, g_xn16);
    cudaGetSymbolAddress((void**)&wqkh, g_wqk_h); cudaGetSymbolAddress((void**)&wqkl, g_wqk_l);
    cudaGetSymbolAddress((void**)&wv16, g_wv16);  cudaGetSymbolAddress((void**)&wo16, g_wo16);
    cudaGetSymbolAddress((void**)&qfh,  g_qf_h);  cudaGetSymbolAddress((void**)&qfl,  g_qf_l);
    cudaGetSymbolAddress((void**)&kfh,  g_kf_h);  cudaGetSymbolAddress((void**)&kfl,  g_kf_l);
    cudaGetSymbolAddress((void**)&vf,   g_vf);    cudaGetSymbolAddress((void**)&ao16, g_ao16);
    cudaGetSymbolAddress((void**)&qk,   g_qk);    cudaGetSymbolAddress((void**)&vbuf, g_v);

    cudaFuncSetAttribute(proj_fused, cudaFuncAttributeMaxDynamicSharedMemorySize, SMEM_64K);
    cudaFuncSetAttribute(gemm_f16s,  cudaFuncAttributeMaxDynamicSharedMemorySize, SMEM_64K);
    cudaFuncSetAttribute(attn_bf,    cudaFuncAttributeMaxDynamicSharedMemorySize, SMEM_ATT);

    // prep: LN (4096 blocks) + coalesced weight conversion (1024 blocks)
    prep_kernel<<<TOK + 1024, 256>>>(x, ln_w, ln_b, xnh, xnl, xn16,
                                     Wq, Wkv, Wo, wqkh, wqkl, wv16, wo16);

    // fused QK (bf16x3) + V (fp16) projections in one launch
    proj_fused<<<dim3(24, TOK / 128), 256, SMEM_64K>>>(xnh, xnl, xn16,
                                                       wqkh, wqkl, wv16, qk, vbuf);

    rms_kernel<<<TOK / 2, 256>>>(qk, vbuf, qg, kg, qfh, qfl, kfh, kfl, vf);

    attn_bf<<<dim3(Sq / 64, Bz * Hn), 128, SMEM_ATT>>>(qfh, qfl, kfh, kfl, vf, ao16);

    // output projection (fp16 single)
    gemm_f16s<<<dim3(DIM / 128, TOK / 128), 256, SMEM_64K>>>(ao16, wo16, out, DIM, INNER);
}

// round 13
// speedup vs baseline: 1.0470x; 1.0015x over previous
#include <cuda_runtime.h>
#include <cuda_bf16.h>
#include <cuda_fp16.h>
#include <cstdint>

#define Bz    2
#define Sq    2048
#define DIM   1024
#define Hn    16
#define DHd   64
#define INNER 1024
#define TOK   4096

// ---------------------------------------------------------------------------
// Scratch (device globals). Fragment arrays are uint32 (packed 16-bit x2).
// ---------------------------------------------------------------------------
__device__ uint32_t g_xn_h[TOK*DIM/2],     g_xn_l[TOK*DIM/2];   // bf16 hi/lo A-frags
__device__ uint32_t g_xn16[TOK*DIM/2];                          // fp16 single A-frags
__device__ uint32_t g_wqk_h[DIM*2048/2],   g_wqk_l[DIM*2048/2]; // Wq|Wk bf16 B-frags
__device__ uint32_t g_wv16[DIM*INNER/2];                        // Wv fp16 B-frags
__device__ uint32_t g_wo16[INNER*DIM/2];                        // Wo fp16 B-frags
__device__ float    g_qk[TOK*2048];                             // q|k projection (fp32)
__device__ float    g_v [TOK*INNER];                            // v projection (fp32)
__device__ uint32_t g_qf_h[TOK*INNER/2],   g_qf_l[TOK*INNER/2]; // fp16 hi/lo
__device__ uint32_t g_kf_h[TOK*INNER/2],   g_kf_l[TOK*INNER/2]; // fp16 hi/lo
__device__ uint32_t g_vf  [TOK*INNER/2];                        // fp16 single
__device__ uint32_t g_ao16[TOK*INNER/2];                        // attn out fp16 A-frags

// ---------------------------------------------------------------------------
// Helpers
// ---------------------------------------------------------------------------
__device__ __forceinline__ uint32_t smem_u32(const void* p) {
    uint32_t a;
    asm("{ .reg .u64 t; cvta.to.shared.u64 t, %1; cvt.u32.u64 %0, t; }" : "=r"(a) : "l"(p));
    return a;
}
__device__ __forceinline__ uint32_t pkbf(float a, float b) {
    return (uint32_t)__bfloat16_as_ushort(__float2bfloat16_rn(a)) |
           ((uint32_t)__bfloat16_as_ushort(__float2bfloat16_rn(b)) << 16);
}
__device__ __forceinline__ void splitbf(float a, float b, uint32_t& hi, uint32_t& lo) {
    __nv_bfloat16 ha = __float2bfloat16_rn(a), hb = __float2bfloat16_rn(b);
    hi = (uint32_t)__bfloat16_as_ushort(ha) | ((uint32_t)__bfloat16_as_ushort(hb) << 16);
    lo = pkbf(a - __bfloat162float(ha), b - __bfloat162float(hb));
}
__device__ __forceinline__ uint32_t pkh2(float a, float b) {
    __half2 h = __floats2half2_rn(a, b);
    return *(uint32_t*)&h;
}
__device__ __forceinline__ void splitf16(float a, float b, uint32_t& hi, uint32_t& lo) {
    __half ha = __float2half_rn(a), hb = __float2half_rn(b);
    __half2 hp = __halves2half2(ha, hb);
    hi = *(uint32_t*)&hp;
    lo = pkh2(a - __half2float(ha), b - __half2float(hb));
}
__device__ __forceinline__ float ex2(float x) {
    float y;
    asm("ex2.approx.f32 %0, %1;" : "=f"(y) : "f"(x));
    return y;
}
// exp2 of two fp32 values -> packed fp16x2 {lo=exp2(a), hi=exp2(b)}
__device__ __forceinline__ uint32_t ex2h2(float a, float b) {
    uint32_t r;
    asm("{ .reg .b32 t; cvt.rn.f16x2.f32 t, %2, %1; ex2.approx.f16x2 %0, t; }"
        : "=r"(r) : "f"(a), "f"(b));
    return r;
}
__device__ __forceinline__ uint32_t hadd2u(uint32_t a, uint32_t b) {
    uint32_t r;
    asm("add.f16x2 %0, %1, %2;" : "=r"(r) : "r"(a), "r"(b));
    return r;
}
__device__ __forceinline__ float2 h22f2(uint32_t h) {
    __half2 hh = *(__half2*)&h;
    return __half22float2(hh);
}
__device__ __forceinline__ void mma_bf(float* c, const uint32_t* a, const uint32_t* b) {
    asm volatile(
        "mma.sync.aligned.m16n8k16.row.col.f32.bf16.bf16.f32 "
        "{%0,%1,%2,%3}, {%4,%5,%6,%7}, {%8,%9}, {%0,%1,%2,%3};"
        : "+f"(c[0]), "+f"(c[1]), "+f"(c[2]), "+f"(c[3])
        : "r"(a[0]), "r"(a[1]), "r"(a[2]), "r"(a[3]), "r"(b[0]), "r"(b[1]));
}
__device__ __forceinline__ void mma_f16(float* c, const uint32_t* a, const uint32_t* b) {
    asm volatile(
        "mma.sync.aligned.m16n8k16.row.col.f32.f16.f16.f32 "
        "{%0,%1,%2,%3}, {%4,%5,%6,%7}, {%8,%9}, {%0,%1,%2,%3};"
        : "+f"(c[0]), "+f"(c[1]), "+f"(c[2]), "+f"(c[3])
        : "r"(a[0]), "r"(a[1]), "r"(a[2]), "r"(a[3]), "r"(b[0]), "r"(b[1]));
}
__device__ __forceinline__ void cpa16(uint32_t saddr, const void* gptr) {
    asm volatile("cp.async.cg.shared.global [%0], [%1], 16;" :: "r"(saddr), "l"(gptr) : "memory");
}
__device__ __forceinline__ void cp_commit() { asm volatile("cp.async.commit_group;" ::: "memory"); }
template <int N> __device__ __forceinline__ void cp_wait() {
    asm volatile("cp.async.wait_group %0;" :: "n"(N) : "memory");
}

// ---------------------------------------------------------------------------
// 1) Prep: blocks [0,4096) LayerNorm; [4096,5120) coalesced weight frags.
// ---------------------------------------------------------------------------
__global__ void __launch_bounds__(256) prep_kernel(const float* __restrict__ x,
                                                   const float* __restrict__ w,
                                                   const float* __restrict__ bias,
                                                   uint32_t* __restrict__ xh,
                                                   uint32_t* __restrict__ xl,
                                                   uint32_t* __restrict__ x16,
                                                   const float* __restrict__ Wq,
                                                   const float* __restrict__ Wkv,
                                                   const float* __restrict__ Wo,
                                                   uint32_t* __restrict__ wqkh,
                                                   uint32_t* __restrict__ wqkl,
                                                   uint32_t* __restrict__ wv16,
                                                   uint32_t* __restrict__ wo16) {
    const int bid = blockIdx.x;
    if (bid >= TOK) {
        const int r = bid - TOK;               // [0,1024)
        const int mat = r >> 8;                // 0=Wq 1=Wk 2=Wv 3=Wo
        const int warp = threadIdx.x >> 5, lane = threadIdx.x & 31;
        const int gw = (r & 255) * 8 + warp;   // [0,2048)
        const int pb  = gw & 63;               // K/16 block (KS=64)
        const int nt0 = (gw >> 6) << 2;        // 4 nt per warp
        const int ntl = lane >> 3, g = lane & 7;
        const int nt  = nt0 + ntl;
        const int n_local = nt * 8 + g;

        const float* src;
        int stride, col;
        if (mat == 0)      { src = Wq;  stride = 1024; col = n_local; }
        else if (mat == 1) { src = Wkv; stride = 2048; col = n_local; }
        else if (mat == 2) { src = Wkv; stride = 2048; col = 1024 + n_local; }
        else               { src = Wo;  stride = 1024; col = n_local; }

        float v[16];
#pragma unroll
        for (int i = 0; i < 16; i++)
            v[i] = src[(size_t)(16 * pb + i) * stride + col];

        if (mat <= 1) {
            uint32_t hiw[8], low[8];
#pragma unroll
            for (int o = 0; o < 8; o++) {
                const int pl = ((o & 1) << 2) + (o >> 1);
                splitbf(v[2 * pl], v[2 * pl + 1], hiw[o], low[o]);
            }
            const int out_nt = (mat == 0 ? 0 : 128) + nt;
            const size_t base = ((size_t)(out_nt * 64 + pb)) * 64 + g * 8;
            *(uint4*)(wqkh + base)     = make_uint4(hiw[0], hiw[1], hiw[2], hiw[3]);
            *(uint4*)(wqkh + base + 4) = make_uint4(hiw[4], hiw[5], hiw[6], hiw[7]);
            *(uint4*)(wqkl + base)     = make_uint4(low[0], low[1], low[2], low[3]);
            *(uint4*)(wqkl + base + 4) = make_uint4(low[4], low[5], low[6], low[7]);
        } else {
            uint32_t wd[8];
#pragma unroll
            for (int o = 0; o < 8; o++) {
                const int pl = ((o & 1) << 2) + (o >> 1);
                wd[o] = pkh2(v[2 * pl], v[2 * pl + 1]);
            }
            uint32_t* dst = (mat == 2) ? wv16 : wo16;
            const size_t base = ((size_t)(nt * 64 + pb)) * 64 + g * 8;
            *(uint4*)(dst + base)     = make_uint4(wd[0], wd[1], wd[2], wd[3]);
            *(uint4*)(dst + base + 4) = make_uint4(wd[4], wd[5], wd[6], wd[7]);
        }
        return;
    }
    const int row = bid;
    const float* xr = x + (size_t)row * DIM;
    float2 v[2];
    v[0] = *(const float2*)(xr + 2 * threadIdx.x);
    v[1] = *(const float2*)(xr + 2 * (threadIdx.x + 256));
    float s  = v[0].x + v[0].y + v[1].x + v[1].y;
    float sq = v[0].x * v[0].x + v[0].y * v[0].y + v[1].x * v[1].x + v[1].y * v[1].y;
#pragma unroll
    for (int off = 16; off; off >>= 1) {
        s  += __shfl_xor_sync(0xffffffffu, s, off);
        sq += __shfl_xor_sync(0xffffffffu, sq, off);
    }
    __shared__ float red[2][8];
    const int warp = threadIdx.x >> 5, lane = threadIdx.x & 31;
    if (lane == 0) { red[0][warp] = s; red[1][warp] = sq; }
    __syncthreads();
    float ts = 0.f, tq2 = 0.f;
#pragma unroll
    for (int i = 0; i < 8; i++) { ts += red[0][i]; tq2 += red[1][i]; }
    const float mean = ts * (1.0f / DIM);
    const float var  = tq2 * (1.0f / DIM) - mean * mean;
    const float rstd = rsqrtf(var + 1e-5f);
    const int mt = row >> 4, mr = row & 15, g = mr & 7, hih = mr >> 3;
#pragma unroll
    for (int i = 0; i < 2; i++) {
        const int p = threadIdx.x + i * 256;
        const float2 wv = *(const float2*)(w + 2 * p);
        const float2 bv = *(const float2*)(bias + 2 * p);
        const float y0 = wv.x * (v[i].x - mean) * rstd + bv.x;
        const float y1 = wv.y * (v[i].y - mean) * rstd + bv.y;
        const int ks = p >> 3, c = p & 7, tq = c & 3, ch = c >> 2;
        const size_t idx = ((size_t)(mt * 64 + ks)) * 128 + (g * 4 + tq) * 4 + hih + 2 * ch;
        uint32_t hi, lo;
        splitbf(y0, y1, hi, lo);
        xh[idx] = hi; xl[idx] = lo;
        x16[idx] = pkh2(y0, y1);
    }
}

// ---------------------------------------------------------------------------
// 2a) bf16x3 GEMM body: 128x128 tile, BK=32, 2-stage cp.async.
// ---------------------------------------------------------------------------
__device__ __forceinline__ void gemm_bf3_body(const uint32_t* __restrict__ Ah,
                                              const uint32_t* __restrict__ Al,
                                              const uint32_t* __restrict__ Bh,
                                              const uint32_t* __restrict__ Bl,
                                              float* __restrict__ C,
                                              int N, int K, int bm, int bn,
                                              uint32_t* sm) {
    const int tid = threadIdx.x, wid = tid >> 5, lane = tid & 31;
    const int wr = wid >> 2, wc = wid & 3, g = lane >> 2, tq = lane & 3;
    const int KS = K >> 4, NSTG = K >> 5;
    const uint32_t sbase = smem_u32(sm);

    const uint32_t* Ah0 = Ah + (size_t)(bm >> 4) * KS * 128;
    const uint32_t* Al0 = Al + (size_t)(bm >> 4) * KS * 128;
    const uint32_t* Bh0 = Bh + (size_t)(bn >> 3) * KS * 64;
    const uint32_t* Bl0 = Bl + (size_t)(bn >> 3) * KS * 64;

    float acc[4][4][4];
#pragma unroll
    for (int i = 0; i < 4; i++)
#pragma unroll
        for (int j = 0; j < 4; j++)
#pragma unroll
            for (int e = 0; e < 4; e++) acc[i][j][e] = 0.f;

#define G_ISSUE(S, BUF) do {                                                        \
    const uint32_t sb_ = sbase + (uint32_t)(BUF) * 32768u;                          \
    _Pragma("unroll")                                                               \
    for (int i_ = 0; i_ < 2; i_++) {                                                \
        const int f_ = tid + i_ * 256;                                              \
        const int mt_ = f_ >> 6, wA_ = (4 * f_) & 255;                              \
        const int ksA_ = wA_ >> 7, frA_ = wA_ & 127;                                \
        const size_t oa_ = ((size_t)mt_ * KS + (S) * 2 + ksA_) * 128 + frA_;        \
        cpa16(sb_ + f_ * 16u,           Ah0 + oa_);                                 \
        cpa16(sb_ + 8192u + f_ * 16u,   Al0 + oa_);                                 \
        const int nt_ = f_ >> 5, wB_ = (4 * f_) & 127;                              \
        const int ksB_ = wB_ >> 6, frB_ = wB_ & 63;                                 \
        const size_t ob_ = ((size_t)nt_ * KS + (S) * 2 + ksB_) * 64 + frB_;         \
        cpa16(sb_ + 16384u + f_ * 16u,  Bh0 + ob_);                                 \
        cpa16(sb_ + 24576u + f_ * 16u,  Bl0 + ob_);                                 \
    }                                                                               \
    cp_commit();                                                                    \
} while (0)

    G_ISSUE(0, 0);
    int buf = 0;
    for (int s = 0; s < NSTG; s++) {
        if (s + 1 < NSTG) { G_ISSUE(s + 1, buf ^ 1); cp_wait<1>(); }
        else              { cp_wait<0>(); }
        __syncthreads();
        const uint32_t* S0 = sm + buf * 8192;
#pragma unroll
        for (int ksl = 0; ksl < 2; ksl++) {
            uint4 ah[4], al[4];
            uint2 bh[4], bl[4];
#pragma unroll
            for (int i = 0; i < 4; i++) {
                const int mt = wr * 4 + i;
                ah[i] = *(const uint4*)(S0 + (mt * 2 + ksl) * 128 + (g * 4 + tq) * 4);
                al[i] = *(const uint4*)(S0 + 2048 + (mt * 2 + ksl) * 128 + (g * 4 + tq) * 4);
            }
#pragma unroll
            for (int j = 0; j < 4; j++) {
                const int nt = wc * 4 + j;
                bh[j] = *(const uint2*)(S0 + 4096 + (nt * 2 + ksl) * 64 + (g * 4 + tq) * 2);
                bl[j] = *(const uint2*)(S0 + 6144 + (nt * 2 + ksl) * 64 + (g * 4 + tq) * 2);
            }
#pragma unroll
            for (int i = 0; i < 4; i++)
#pragma unroll
                for (int j = 0; j < 4; j++) {
                    mma_bf(acc[i][j], (const uint32_t*)&ah[i], (const uint32_t*)&bh[j]);
                    mma_bf(acc[i][j], (const uint32_t*)&ah[i], (const uint32_t*)&bl[j]);
                    mma_bf(acc[i][j], (const uint32_t*)&al[i], (const uint32_t*)&bh[j]);
                }
        }
        __syncthreads();
        buf ^= 1;
    }
#undef G_ISSUE

#pragma unroll
    for (int i = 0; i < 4; i++) {
        const int r0 = bm + (wr * 4 + i) * 16 + g;
#pragma unroll
        for (int j = 0; j < 4; j++) {
            const int c0 = bn + (wc * 4 + j) * 8 + 2 * tq;
            *(float2*)(C + (size_t)r0 * N + c0)       = make_float2(acc[i][j][0], acc[i][j][1]);
            *(float2*)(C + (size_t)(r0 + 8) * N + c0) = make_float2(acc[i][j][2], acc[i][j][3]);
        }
    }
}

// ---------------------------------------------------------------------------
// 2b) fp16-single GEMM body: 128x128 tile, BK=64, 2-stage cp.async, 1 MMA.
// ---------------------------------------------------------------------------
__device__ __forceinline__ void gemm_f16s_body(const uint32_t* __restrict__ Af,
                                               const uint32_t* __restrict__ Bf,
                                               float* __restrict__ C,
                                               int N, int K, int bm, int bn,
                                               uint32_t* sm) {
    const int tid = threadIdx.x, wid = tid >> 5, lane = tid & 31;
    const int wr = wid >> 2, wc = wid & 3, g = lane >> 2, tq = lane & 3;
    const int KS = K >> 4, NSTG = K >> 6;
    const uint32_t sbase = smem_u32(sm);

    const uint32_t* A0g = Af + (size_t)(bm >> 4) * KS * 128;
    const uint32_t* B0g = Bf + (size_t)(bn >> 3) * KS * 64;

    float acc[4][4][4];
#pragma unroll
    for (int i = 0; i < 4; i++)
#pragma unroll
        for (int j = 0; j < 4; j++)
#pragma unroll
            for (int e = 0; e < 4; e++) acc[i][j][e] = 0.f;

#define F_ISSUE(S, BUF) do {                                                        \
    const uint32_t sb_ = sbase + (uint32_t)(BUF) * 32768u;                          \
    _Pragma("unroll")                                                               \
    for (int i_ = 0; i_ < 4; i_++) {                                                \
        const int f_ = tid + i_ * 256;                                              \
        const int mt_ = f_ >> 7, wA_ = (4 * f_) & 511;                              \
        const int ksA_ = wA_ >> 7, frA_ = wA_ & 127;                                \
        const size_t oa_ = ((size_t)mt_ * KS + (S) * 4 + ksA_) * 128 + frA_;        \
        cpa16(sb_ + f_ * 16u, A0g + oa_);                                           \
        const int nt_ = f_ >> 6, wB_ = (4 * f_) & 255;                              \
        const int ksB_ = wB_ >> 6, frB_ = wB_ & 63;                                 \
        const size_t ob_ = ((size_t)nt_ * KS + (S) * 4 + ksB_) * 64 + frB_;         \
        cpa16(sb_ + 16384u + f_ * 16u, B0g + ob_);                                  \
    }                                                                               \
    cp_commit();                                                                    \
} while (0)

    F_ISSUE(0, 0);
    int buf = 0;
    for (int s = 0; s < NSTG; s++) {
        if (s + 1 < NSTG) { F_ISSUE(s + 1, buf ^ 1); cp_wait<1>(); }
        else              { cp_wait<0>(); }
        __syncthreads();
        const uint32_t* S0 = sm + buf * 8192;
#pragma unroll
        for (int ksl = 0; ksl < 4; ksl++) {
            uint4 a[4];
            uint2 b[4];
#pragma unroll
            for (int i = 0; i < 4; i++)
                a[i] = *(const uint4*)(S0 + ((wr * 4 + i) * 4 + ksl) * 128 + (g * 4 + tq) * 4);
#pragma unroll
            for (int j = 0; j < 4; j++)
                b[j] = *(const uint2*)(S0 + 4096 + ((wc * 4 + j) * 4 + ksl) * 64 + (g * 4 + tq) * 2);
#pragma unroll
            for (int i = 0; i < 4; i++)
#pragma unroll
                for (int j = 0; j < 4; j++)
                    mma_f16(acc[i][j], (const uint32_t*)&a[i], (const uint32_t*)&b[j]);
        }
        __syncthreads();
        buf ^= 1;
    }
#undef F_ISSUE

#pragma unroll
    for (int i = 0; i < 4; i++) {
        const int r0 = bm + (wr * 4 + i) * 16 + g;
#pragma unroll
        for (int j = 0; j < 4; j++) {
            const int c0 = bn + (wc * 4 + j) * 8 + 2 * tq;
            *(float2*)(C + (size_t)r0 * N + c0)       = make_float2(acc[i][j][0], acc[i][j][1]);
            *(float2*)(C + (size_t)(r0 + 8) * N + c0) = make_float2(acc[i][j][2], acc[i][j][3]);
        }
    }
}

// Fused QK (bf16x3) + V (fp16) projection: grid (24, 32).
__global__ void __launch_bounds__(256, 2) proj_fused(const uint32_t* __restrict__ xh,
                                                     const uint32_t* __restrict__ xl,
                                                     const uint32_t* __restrict__ x16,
                                                     const uint32_t* __restrict__ wqkh,
                                                     const uint32_t* __restrict__ wqkl,
                                                     const uint32_t* __restrict__ wv16,
                                                     float* __restrict__ qk,
                                                     float* __restrict__ v) {
    extern __shared__ uint32_t sm[];
    if (blockIdx.x < 16)
        gemm_bf3_body(xh, xl, wqkh, wqkl, qk, 2048, 1024,
                      blockIdx.y * 128, blockIdx.x * 128, sm);
    else
        gemm_f16s_body(x16, wv16, v, 1024, 1024,
                       blockIdx.y * 128, (blockIdx.x - 16) * 128, sm);
}

// Standalone fp16-single GEMM (output projection).
__global__ void __launch_bounds__(256, 2) gemm_f16s(const uint32_t* __restrict__ Af,
                                                    const uint32_t* __restrict__ Bf,
                                                    float* __restrict__ C,
                                                    int N, int K) {
    extern __shared__ uint32_t sm[];
    gemm_f16s_body(Af, Bf, C, N, K, blockIdx.y * 128, blockIdx.x * 128, sm);
}

// ---------------------------------------------------------------------------
// 3) RMSNorm + head-split: Q, K -> fp16 hi/lo frags; V -> single fp16 B-frags.
// ---------------------------------------------------------------------------
#define LOG2E 1.4426950408889634f

__global__ void __launch_bounds__(256) rms_kernel(const float* __restrict__ qk,
                                                  const float* __restrict__ vv,
                                                  const float* __restrict__ qg,
                                                  const float* __restrict__ kg,
                                                  uint32_t* __restrict__ qfh, uint32_t* __restrict__ qfl,
                                                  uint32_t* __restrict__ kfh, uint32_t* __restrict__ kfl,
                                                  uint32_t* __restrict__ vf) {
    const int tk0 = blockIdx.x * 2;
    const int warp = threadIdx.x >> 5, lane = threadIdx.x & 31;
    const int b = tk0 >> 11, s0 = tk0 & 2047;
    const int ks = lane >> 3, c = lane & 7, tq = c & 3, ch = c >> 2;
#pragma unroll
    for (int i = 0; i < 2; i++) {
        const int h = warp * 2 + i;
        const int bh = b * 16 + h;
        const float2 gq = *(const float2*)(qg + h * 64 + 2 * lane);
        const float2 gk = *(const float2*)(kg + h * 64 + 2 * lane);
#pragma unroll
        for (int tt = 0; tt < 2; tt++) {
            const int token = tk0 + tt, s = s0 + tt;
            {
                const float2 qv = *(const float2*)(qk + (size_t)token * 2048 + h * 64 + 2 * lane);
                float ss = qv.x * qv.x + qv.y * qv.y;
#pragma unroll
                for (int off = 16; off; off >>= 1) ss += __shfl_xor_sync(0xffffffffu, ss, off);
                const float r = rsqrtf(ss * (1.0f / DHd) + 1e-8f) * (8.0f * LOG2E);
                const int mt = s >> 4, mr = s & 15, gg = mr & 7, hih = mr >> 3;
                const size_t qi = ((size_t)(bh * 128 + mt) * 4 + ks) * 128 + (gg * 4 + tq) * 4 + hih + 2 * ch;
                uint32_t hi, lo;
                splitf16(qv.x * r * gq.x, qv.y * r * gq.y, hi, lo);
                qfh[qi] = hi; qfl[qi] = lo;
            }
            {
                const float2 kvv = *(const float2*)(qk + (size_t)token * 2048 + 1024 + h * 64 + 2 * lane);
                float ss = kvv.x * kvv.x + kvv.y * kvv.y;
#pragma unroll
                for (int off = 16; off; off >>= 1) ss += __shfl_xor_sync(0xffffffffu, ss, off);
                const float r = rsqrtf(ss * (1.0f / DHd) + 1e-8f) * 8.0f;
                const int nt = s >> 3, gg = s & 7;
                const size_t ki = ((size_t)(bh * 256 + nt) * 4 + ks) * 64 + (gg * 4 + tq) * 2 + ch;
                uint32_t hi, lo;
                splitf16(kvv.x * r * gk.x, kvv.y * r * gk.y, hi, lo);
                kfh[ki] = hi; kfl[ki] = lo;
            }
        }
        {
            const float2 va = *(const float2*)(vv + (size_t)tk0 * 1024 + h * 64 + 2 * lane);
            const float2 vb = *(const float2*)(vv + (size_t)(tk0 + 1) * 1024 + h * 64 + 2 * lane);
            const int pq = s0 >> 1;
            const int ksv = pq >> 3, cv = pq & 7, tv = cv & 3, rv = cv >> 2;
            const int d0 = 2 * lane;
            const size_t vi0 = ((size_t)(bh * 128 + ksv) * 8 + (d0 >> 3)) * 64 + ((d0 & 7) * 4 + tv) * 2 + rv;
            const size_t vi1 = ((size_t)(bh * 128 + ksv) * 8 + ((d0 + 1) >> 3)) * 64 + (((d0 + 1) & 7) * 4 + tv) * 2 + rv;
            vf[vi0] = pkh2(va.x, vb.x);
            vf[vi1] = pkh2(va.y, vb.y);
        }
    }
}

// ---------------------------------------------------------------------------
// 4) Flash attention: fp16 MMA, f16x2 exp, guarded rescale, and per-k2
//    exp->PV interleave with deferred l-reduction (bit-exact reorder of R12).
//    CTA = 4 warps / 64 Q rows, 2-stage 48KB pipeline -> 4 CTAs/SM.
// ---------------------------------------------------------------------------
__global__ void __launch_bounds__(128, 4) attn_bf(const uint32_t* __restrict__ Qh,
                                                  const uint32_t* __restrict__ Ql,
                                                  const uint32_t* __restrict__ Kh,
                                                  const uint32_t* __restrict__ Kl,
                                                  const uint32_t* __restrict__ Vf,
                                                  uint32_t* __restrict__ O16) {
    extern __shared__ uint32_t sm[];
    const int tid = threadIdx.x, warp = tid >> 5, lane = tid & 31;
    const int g = lane >> 2, tq = lane & 3;
    const int bh = blockIdx.y, h = bh & 15;
    const uint32_t sbase = smem_u32(sm);

    uint4 qh_[4], ql_[4];
    {
        const size_t qb = ((size_t)(bh * 128 + blockIdx.x * 4 + warp)) * 4;
#pragma unroll
        for (int ks = 0; ks < 4; ks++) {
            qh_[ks] = *(const uint4*)(Qh + (qb + ks) * 128 + (g * 4 + tq) * 4);
            ql_[ks] = *(const uint4*)(Ql + (qb + ks) * 128 + (g * 4 + tq) * 4);
        }
    }

    const uint32_t* Kh0 = Kh + (size_t)bh * 65536;
    const uint32_t* Kl0 = Kl + (size_t)bh * 65536;
    const uint32_t* Vf0 = Vf + (size_t)bh * 65536;

    float oacc[8][4];
#pragma unroll
    for (int j = 0; j < 8; j++)
#pragma unroll
        for (int e = 0; e < 4; e++) oacc[j][e] = 0.f;
    float m0 = -1e30f, m1 = -1e30f, l0 = 0.f, l1 = 0.f;

#define A_ISSUE(T, BUF) do {                                                  \
    const uint32_t sb_ = sbase + (uint32_t)(BUF) * 24576u;                    \
    _Pragma("unroll")                                                         \
    for (int i_ = 0; i_ < 4; i_++) {                                          \
        const int f_ = tid + i_ * 128;                                        \
        const size_t o_ = (size_t)(T) * 2048 + 4 * f_;                        \
        cpa16(sb_ + f_ * 16u,          Kh0 + o_);                             \
        cpa16(sb_ + 8192u + f_ * 16u,  Kl0 + o_);                             \
        cpa16(sb_ + 16384u + f_ * 16u, Vf0 + o_);                             \
    }                                                                         \
    cp_commit();                                                              \
} while (0)

    A_ISSUE(0, 0);
    int buf = 0;
    const int NT = Sq / 64;
    for (int t = 0; t < NT; t++) {
        if (t + 1 < NT) { A_ISSUE(t + 1, buf ^ 1); cp_wait<1>(); }
        else            { cp_wait<0>(); }
        __syncthreads();
        const uint32_t* SKh = sm + buf * 6144;
        const uint32_t* SKl = SKh + 2048;
        const uint32_t* SV  = SKh + 4096;

        float sacc[8][4];
#pragma unroll
        for (int j = 0; j < 8; j++)
#pragma unroll
            for (int e = 0; e < 4; e++) sacc[j][e] = 0.f;
#pragma unroll
        for (int ks = 0; ks < 4; ks++) {
#pragma unroll
            for (int j = 0; j < 8; j++) {
                const uint2 kbh = *(const uint2*)(SKh + (j * 4 + ks) * 64 + (g * 4 + tq) * 2);
                const uint2 kbl = *(const uint2*)(SKl + (j * 4 + ks) * 64 + (g * 4 + tq) * 2);
                mma_f16(sacc[j], (const uint32_t*)&qh_[ks], (const uint32_t*)&kbh);
                mma_f16(sacc[j], (const uint32_t*)&qh_[ks], (const uint32_t*)&kbl);
                mma_f16(sacc[j], (const uint32_t*)&ql_[ks], (const uint32_t*)&kbh);
            }
        }

        float mx0 = -1e30f, mx1 = -1e30f;
#pragma unroll
        for (int j = 0; j < 8; j++) {
            mx0 = fmaxf(mx0, fmaxf(sacc[j][0], sacc[j][1]));
            mx1 = fmaxf(mx1, fmaxf(sacc[j][2], sacc[j][3]));
        }
        mx0 = fmaxf(mx0, __shfl_xor_sync(0xffffffffu, mx0, 1));
        mx0 = fmaxf(mx0, __shfl_xor_sync(0xffffffffu, mx0, 2));
        mx1 = fmaxf(mx1, __shfl_xor_sync(0xffffffffu, mx1, 1));
        mx1 = fmaxf(mx1, __shfl_xor_sync(0xffffffffu, mx1, 2));
        const float nm0 = fmaxf(m0, mx0), nm1 = fmaxf(m1, mx1);

        // Rescale only if ANY lane's row max changed (bit-exact skip: c==1).
        const bool upd = (nm0 != m0) || (nm1 != m1);
        if (__any_sync(0xffffffffu, upd)) {
            const float c0 = ex2(m0 - nm0), c1 = ex2(m1 - nm1);
            l0 *= c0; l1 *= c1;
#pragma unroll
            for (int j = 0; j < 8; j++) {
                oacc[j][0] *= c0; oacc[j][1] *= c0;
                oacc[j][2] *= c1; oacc[j][3] *= c1;
            }
            m0 = nm0; m1 = nm1;
        }

        // Interleaved exp -> PV per k2 group: exps of group k2+1 dual-issue
        // under the PV MMAs of group k2. l-reduction deferred past all MMAs.
        uint32_t pc0 = 0, pc1 = 0;
#pragma unroll
        for (int k2 = 0; k2 < 4; k2++) {
            uint32_t pa[4];
            {
                const int j0 = 2 * k2, j1 = 2 * k2 + 1;
                const uint32_t a0 = ex2h2(sacc[j0][0] - m0, sacc[j0][1] - m0);
                const uint32_t a1 = ex2h2(sacc[j0][2] - m1, sacc[j0][3] - m1);
                const uint32_t a2 = ex2h2(sacc[j1][0] - m0, sacc[j1][1] - m0);
                const uint32_t a3 = ex2h2(sacc[j1][2] - m1, sacc[j1][3] - m1);
                pc0 = hadd2u(pc0, a0); pc1 = hadd2u(pc1, a1);
                pc0 = hadd2u(pc0, a2); pc1 = hadd2u(pc1, a3);
                pa[0] = a0; pa[1] = a1; pa[2] = a2; pa[3] = a3;
            }
#pragma unroll
            for (int j = 0; j < 8; j++) {
                const uint2 vb = *(const uint2*)(SV + (k2 * 8 + j) * 64 + (g * 4 + tq) * 2);
                mma_f16(oacc[j], pa, (const uint32_t*)&vb);
            }
        }

        // Deferred l-reduction (shuffles drain while tensor pipe is busy).
        const float2 f0 = h22f2(pc0), f1 = h22f2(pc1);
        float ls0 = f0.x + f0.y, ls1 = f1.x + f1.y;
        ls0 += __shfl_xor_sync(0xffffffffu, ls0, 1);
        ls0 += __shfl_xor_sync(0xffffffffu, ls0, 2);
        ls1 += __shfl_xor_sync(0xffffffffu, ls1, 1);
        ls1 += __shfl_xor_sync(0xffffffffu, ls1, 2);
        l0 += ls0; l1 += ls1;

        __syncthreads();
        buf ^= 1;
    }
#undef A_ISSUE

    const float inv0 = 1.0f / l0, inv1 = 1.0f / l1;
    const int mt_o = (bh >> 4) * 128 + blockIdx.x * 4 + warp;
#pragma unroll
    for (int j = 0; j < 8; j++) {
        const size_t ix0 = ((size_t)(mt_o * 64 + h * 4 + (j >> 1))) * 128 + (g * 4 + tq) * 4 + 2 * (j & 1);
        O16[ix0]     = pkh2(oacc[j][0] * inv0, oacc[j][1] * inv0);
        O16[ix0 + 1] = pkh2(oacc[j][2] * inv1, oacc[j][3] * inv1);
    }
}

// ---------------------------------------------------------------------------
// Launcher
// ---------------------------------------------------------------------------
#define SMEM_64K 65536
#define SMEM_ATT 49152

extern "C" void kernel_launch(void* const* d_in, const int* in_sizes, int n_in,
                              void* d_out, int out_size) {
    const float* x    = (const float*)d_in[0];
    const float* ln_w = (const float*)d_in[1];
    const float* ln_b = (const float*)d_in[2];
    const float* Wq   = (const float*)d_in[3];
    const float* Wkv  = (const float*)d_in[4];
    const float* qg   = (const float*)d_in[5];
    const float* kg   = (const float*)d_in[6];
    const float* Wo   = (const float*)d_in[7];
    float* out = (float*)d_out;

    uint32_t *xnh, *xnl, *xn16, *wqkh, *wqkl, *wv16, *wo16;
    uint32_t *qfh, *qfl, *kfh, *kfl, *vf, *ao16;
    float *qk, *vbuf;
    cudaGetSymbolAddress((void**)&xnh,  g_xn_h);  cudaGetSymbolAddress((void**)&xnl,  g_xn_l);
    cudaGetSymbolAddress((void**)&xn16, g_xn16);
    cudaGetSymbolAddress((void**)&wqkh, g_wqk_h); cudaGetSymbolAddress((void**)&wqkl, g_wqk_l);
    cudaGetSymbolAddress((void**)&wv16, g_wv16);  cudaGetSymbolAddress((void**)&wo16, g_wo16);
    cudaGetSymbolAddress((void**)&qfh,  g_qf_h);  cudaGetSymbolAddress((void**)&qfl,  g_qf_l);
    cudaGetSymbolAddress((void**)&kfh,  g_kf_h);  cudaGetSymbolAddress((void**)&kfl,  g_kf_l);
    cudaGetSymbolAddress((void**)&vf,   g_vf);    cudaGetSymbolAddress((void**)&ao16, g_ao16);
    cudaGetSymbolAddress((void**)&qk,   g_qk);    cudaGetSymbolAddress((void**)&vbuf, g_v);

    cudaFuncSetAttribute(proj_fused, cudaFuncAttributeMaxDynamicSharedMemorySize, SMEM_64K);
    cudaFuncSetAttribute(gemm_f16s,  cudaFuncAttributeMaxDynamicSharedMemorySize, SMEM_64K);
    cudaFuncSetAttribute(attn_bf,    cudaFuncAttributeMaxDynamicSharedMemorySize, SMEM_ATT);

    // prep: LN (4096 blocks) + coalesced weight conversion (1024 blocks)
    prep_kernel<<<TOK + 1024, 256>>>(x, ln_w, ln_b, xnh, xnl, xn16,
                                     Wq, Wkv, Wo, wqkh, wqkl, wv16, wo16);

    // fused QK (bf16x3) + V (fp16) projections in one launch
    proj_fused<<<dim3(24, TOK / 128), 256, SMEM_64K>>>(xnh, xnl, xn16,
                                                       wqkh, wqkl, wv16, qk, vbuf);

    rms_kernel<<<TOK / 2, 256>>>(qk, vbuf, qg, kg, qfh, qfl, kfh, kfl, vf);

    attn_bf<<<dim3(Sq / 64, Bz * Hn), 128, SMEM_ATT>>>(qfh, qfl, kfh, kfl, vf, ao16);

    // output projection (fp16 single)
    gemm_f16s<<<dim3(DIM / 128, TOK / 128), 256, SMEM_64K>>>(ao16, wo16, out, DIM, INNER);
}